// round 11
// baseline (speedup 1.0000x reference)
#include <cuda_runtime.h>
#include <cuda_fp16.h>
#include <cstdint>

#define Hh   128
#define Ww   128
#define HW   16384
#define Cc   128
#define NP   9
#define OUTC 256
#define Bb   4
#define BK   64
#define NT   18

typedef unsigned long long ull;
typedef unsigned int u32;

// -------- device scratch --------
__device__ float g_offset[Bb * 2 * NP * HW];            // (b, 18, H, W)
__device__ __align__(128) __half g_wa[NT * OUTC * BK];  // fp16 A tiles [tile][o][j]
// pre-swizzled fp16 B tiles: [half-job][tile] each 64px x 64k x 2B = 8192 B
__device__ __align__(128) char g_bs[(size_t)(Bb * Hh * 2) * NT * 8192];

// ---------------- helpers ----------------
__device__ __forceinline__ u32 smem_u32(const void* p) {
    u32 a;
    asm("{ .reg .u64 t; cvta.to.shared.u64 t, %1; cvt.u32.u64 %0, t; }" : "=r"(a) : "l"(p));
    return a;
}
__device__ __forceinline__ void ldsm_x4(u32& r0, u32& r1, u32& r2, u32& r3, u32 addr) {
    asm volatile("ldmatrix.sync.aligned.m8n8.x4.shared.b16 {%0,%1,%2,%3}, [%4];"
                 : "=r"(r0), "=r"(r1), "=r"(r2), "=r"(r3) : "r"(addr));
}
__device__ __forceinline__ void mma_f16(float* d, const u32* a, const u32* b) {
    asm("mma.sync.aligned.m16n8k16.row.col.f32.f16.f16.f32 "
        "{%0,%1,%2,%3},{%4,%5,%6,%7},{%8,%9},{%0,%1,%2,%3};"
        : "+f"(d[0]), "+f"(d[1]), "+f"(d[2]), "+f"(d[3])
        : "r"(a[0]), "r"(a[1]), "r"(a[2]), "r"(a[3]), "r"(b[0]), "r"(b[1]));
}
__device__ __forceinline__ u32 swz(u32 off) { return off ^ ((off >> 3) & 0x70); }

__device__ __forceinline__ void cp_async16(u32 dst, const void* src) {
    asm volatile("cp.async.cg.shared.global [%0], [%1], 16;" :: "r"(dst), "l"(src));
}
#define CP_COMMIT() asm volatile("cp.async.commit_group;" ::: "memory")
#define CP_WAIT0()  asm volatile("cp.async.wait_group 0;" ::: "memory")

// packed f32x2 helpers (offset conv)
__device__ __forceinline__ void ffma2(ull& d, ull a, ull b) {
    asm("fma.rn.f32x2 %0, %1, %2, %0;" : "+l"(d) : "l"(a), "l"(b));
}
__device__ __forceinline__ ull pack2(float lo, float hi) {
    ull r; asm("mov.b64 %0, {%1, %2};" : "=l"(r) : "f"(lo), "f"(hi)); return r;
}
__device__ __forceinline__ float2 unpack2(ull v) {
    float2 f; asm("mov.b64 {%0, %1}, %2;" : "=f"(f.x), "=f"(f.y) : "l"(v)); return f;
}

// ======================================================================
// Kernel 1: w_conv (outc, C, N, 1) -> fp16 tiled A: [tile][o][j]
// ======================================================================
__global__ void wtrans_k(const float* __restrict__ wc) {
    int i = blockIdx.x * 256 + threadIdx.x;
    if (i < NT * OUTC * BK) {
        int j = i & 63;
        int o = (i >> 6) & 255;
        int tt = i >> 14;
        int k = tt * 64 + j;
        int n = k >> 7;
        int c = k & 127;
        g_wa[i] = __float2half_rn(wc[(o * Cc + c) * NP + n]);
    }
}

// ======================================================================
// Kernel 2: offset conv (proven, unchanged)
// ======================================================================
__global__ void __launch_bounds__(128) offset_conv_k(
    const float* __restrict__ x,
    const float* __restrict__ wp,
    const float* __restrict__ bp)
{
    const int y0 = blockIdx.x * 2;
    const int b  = blockIdx.y;
    const int tx = threadIdx.x;

    __shared__ float xr[4][132];
    __shared__ float ws2[9][18];

    ull acc0[9], acc1[9];
#pragma unroll
    for (int p = 0; p < 9; p++) { acc0[p] = 0ULL; acc1[p] = 0ULL; }

    const float* xb = x + (size_t)b * Cc * HW;

    for (int c = 0; c < Cc; c++) {
        __syncthreads();
        for (int i = tx; i < 162; i += 128) {
            int k  = i / 18;
            int ch = i % 18;
            ws2[k][ch] = wp[ch * (Cc * 9) + c * 9 + k];
        }
        for (int i = tx; i < 4 * 132; i += 128) {
            int r  = i / 132;
            int cc = i % 132;
            int yy = y0 + r - 1;
            int xx = cc - 1;
            float v = 0.f;
            if (yy >= 0 && yy < Hh && xx >= 0 && xx < Ww)
                v = xb[c * HW + yy * Ww + xx];
            xr[r][cc] = v;
        }
        __syncthreads();

#pragma unroll
        for (int k = 0; k < 9; k++) {
            const int ky = k / 3, kx = k % 3;
            float xv0 = xr[ky][tx + kx];
            float xv1 = xr[ky + 1][tx + kx];
            ull x0d = pack2(xv0, xv0);
            ull x1d = pack2(xv1, xv1);
            const ull* wrow = (const ull*)&ws2[k][0];
#pragma unroll
            for (int p = 0; p < 9; p++) {
                ull wpair = wrow[p];
                ffma2(acc0[p], wpair, x0d);
                ffma2(acc1[p], wpair, x1d);
            }
        }
    }

#pragma unroll
    for (int p = 0; p < 9; p++) {
        float2 a0 = unpack2(acc0[p]);
        float2 a1 = unpack2(acc1[p]);
        int ch0 = 2 * p, ch1 = 2 * p + 1;
        float b0 = bp[ch0], b1 = bp[ch1];
        g_offset[((b * 18 + ch0) * Hh + y0) * Ww + tx]     = a0.x + b0;
        g_offset[((b * 18 + ch1) * Hh + y0) * Ww + tx]     = a0.y + b1;
        g_offset[((b * 18 + ch0) * Hh + y0 + 1) * Ww + tx] = a1.x + b0;
        g_offset[((b * 18 + ch1) * Hh + y0 + 1) * Ww + tx] = a1.y + b1;
    }
}

// ======================================================================
// Kernel 3: bgen — gather + bilinear combine + fp16 pack, write
// pre-swizzled B tiles to gmem scratch. Block = (y, b), 512 threads.
// Thread: px = t & 127 (full row), kq = t >> 7 (16 k per tile).
// ======================================================================
__global__ void __launch_bounds__(512)
bgen_k(const float* __restrict__ x)
{
    __shared__ float4  metaw[NP * 128];
    __shared__ ushort4 metai[NP * 128];

    const int t = threadIdx.x;
    const int y = blockIdx.x;
    const int b = blockIdx.y;

    // ---- bilinear metadata for 128 px x 9 offsets ----
    for (int task = t; task < NP * 128; task += 512) {
        int n  = task >> 7;
        int px = task & 127;
        float offr = g_offset[((b * 18 + n) * Hh + y) * Ww + px];
        float offc = g_offset[((b * 18 + NP + n) * Hh + y) * Ww + px];
        float pr = (float)y  + (float)(n / 3) + offr;
        float pc = (float)px + (float)(n % 3) + offc;

        float ltr = floorf(pr), ltc = floorf(pc);
        float rbr = ltr + 1.f,  rbc = ltc + 1.f;
        ltr = fminf(fmaxf(ltr, 0.f), 127.f);
        rbr = fminf(fmaxf(rbr, 0.f), 127.f);
        ltc = fminf(fmaxf(ltc, 0.f), 127.f);
        rbc = fminf(fmaxf(rbc, 0.f), 127.f);
        pr  = fminf(fmaxf(pr, 0.f), 127.f);
        pc  = fminf(fmaxf(pc, 0.f), 127.f);

        float dr_lt = 1.f + (ltr - pr);
        float dr_rb = 1.f - (rbr - pr);
        float dc_lt = 1.f + (ltc - pc);
        float dc_rb = 1.f - (rbc - pc);

        float4 g;
        g.x = dr_lt * dc_lt;
        g.y = dr_rb * dc_rb;
        g.z = dr_lt * dc_rb;
        g.w = dr_rb * dc_lt;
        metaw[task] = g;

        int iltr = (int)ltr, iltc = (int)ltc;
        int irbr = (int)rbr, irbc = (int)rbc;
        ushort4 iv;
        iv.x = (unsigned short)(iltr * Ww + iltc);
        iv.y = (unsigned short)(irbr * Ww + irbc);
        iv.z = (unsigned short)(iltr * Ww + irbc);
        iv.w = (unsigned short)(irbr * Ww + iltc);
        metai[task] = iv;
    }
    __syncthreads();

    const float* xb = x + (size_t)b * Cc * HW;
    const int px   = t & 127;
    const int kq   = t >> 7;
    const int half = px >> 6;
    const int pxl  = px & 63;

    char* dbase = g_bs + (size_t)(((b * Hh + y) * 2 + half) * NT) * 8192;
    const u32 off0 = swz((u32)(pxl * 128 + kq * 32));
    const u32 off1 = swz((u32)(pxl * 128 + kq * 32 + 16));

    for (int tile = 0; tile < NT; tile++) {
        const int kg0 = tile * BK + kq * 16;
        const int n   = kg0 >> 7;
        const int c0  = kg0 & 127;
        float4  gw = metaw[n * 128 + px];
        ushort4 gi = metai[n * 128 + px];
        const float* xc = xb + (size_t)c0 * HW;
        const float* pA = xc + gi.x;
        const float* pB = xc + gi.y;
        const float* pC = xc + gi.z;
        const float* pD = xc + gi.w;

        u32 pk[8];
#pragma unroll
        for (int u = 0; u < 4; u++) {
            float v[4];
#pragma unroll
            for (int jj = 0; jj < 4; jj++) {
                const int ch = u * 4 + jj;
                v[jj] = gw.x * __ldg(pA + ch * HW) + gw.y * __ldg(pB + ch * HW)
                      + gw.z * __ldg(pC + ch * HW) + gw.w * __ldg(pD + ch * HW);
            }
            asm("cvt.rn.f16x2.f32 %0, %1, %2;" : "=r"(pk[u*2+0]) : "f"(v[1]), "f"(v[0]));
            asm("cvt.rn.f16x2.f32 %0, %1, %2;" : "=r"(pk[u*2+1]) : "f"(v[3]), "f"(v[2]));
        }
        char* d = dbase + (size_t)tile * 8192;
        *(uint4*)(d + off0) = make_uint4(pk[0], pk[1], pk[2], pk[3]);
        *(uint4*)(d + off1) = make_uint4(pk[4], pk[5], pk[6], pk[7]);
    }
}

// ======================================================================
// Kernel 4: pure fp16 GEMM from scratch tiles. CTA = (xhalf, y, b):
// out[b, 0..255, y, xh*64 .. +63]; 256 thr = 8 warps, warp 64x32.
// ======================================================================
#define G_BUFSZ 40960           // A 32768 | B 8192
#define G_BH    32768
#define G_TOTAL (2 * G_BUFSZ)   // 81920

__global__ void __launch_bounds__(256, 2)
gemm_k(float* __restrict__ out)
{
    extern __shared__ char smem[];
    const u32 sb = smem_u32(smem);
    const int t = threadIdx.x;
    const int wid = t >> 5;
    const int lane = t & 31;
    const int xh = blockIdx.x;
    const int y = blockIdx.y;
    const int b = blockIdx.z;

    const char* bsrc = g_bs + (size_t)(((b * Hh + y) * 2 + xh) * NT) * 8192;

    float acc[4][4][4];
#pragma unroll
    for (int i = 0; i < 4; i++)
#pragma unroll
        for (int j = 0; j < 4; j++)
#pragma unroll
            for (int q = 0; q < 4; q++) acc[i][j][q] = 0.f;

    const int bo = (wid & 3) * 64;
    const int bn = (wid >> 2) * 32;

    auto fill_async = [&](int tile) {
        const u32 dst = sb + (u32)(tile & 1) * G_BUFSZ;
        const uint4* srcA = (const uint4*)(g_wa + (size_t)tile * OUTC * BK);
        const uint4* srcB = (const uint4*)(bsrc + (size_t)tile * 8192);
#pragma unroll
        for (int i = 0; i < 8; i++) {
            int e = t + i * 256;
            cp_async16(dst + swz((u32)(e * 16)), srcA + e);
        }
#pragma unroll
        for (int i = 0; i < 2; i++) {
            int e = t + i * 256;
            cp_async16(dst + G_BH + (u32)(e * 16), srcB + e);   // already swizzled
        }
        CP_COMMIT();
    };

    auto compute = [&](int tile) {
        const u32 buf  = sb + (u32)(tile & 1) * G_BUFSZ;
        const u32 bufB = buf + G_BH;
        u32 a[4][4], bf[4][2];
#pragma unroll
        for (int ks = 0; ks < 4; ks++) {
#pragma unroll
            for (int j = 0; j < 2; j++) {
                int nrow = bn + j * 16 + (lane & 7) + ((lane >> 4) << 3);
                int kb   = ks * 32 + ((lane >> 3) & 1) * 16;
                u32 sw = swz((u32)(nrow * 128 + kb));
                ldsm_x4(bf[2*j][0], bf[2*j][1], bf[2*j+1][0], bf[2*j+1][1], bufB + sw);
            }
#pragma unroll
            for (int mi = 0; mi < 4; mi++) {
                int ar = bo + mi * 16 + (lane & 15);
                int kb = ks * 32 + (lane >> 4) * 16;
                u32 sw = swz((u32)(ar * 128 + kb));
                ldsm_x4(a[mi][0], a[mi][1], a[mi][2], a[mi][3], buf + sw);
            }
#pragma unroll
            for (int mi = 0; mi < 4; mi++)
#pragma unroll
                for (int nt = 0; nt < 4; nt++)
                    mma_f16(acc[mi][nt], a[mi], bf[nt]);
        }
    };

    fill_async(0);
    CP_WAIT0();
    __syncthreads();
    for (int tile = 0; tile < NT; tile++) {
        if (tile + 1 < NT) fill_async(tile + 1);
        compute(tile);
        CP_WAIT0();
        __syncthreads();
    }

    const int g  = lane >> 2;
    const int tg = lane & 3;
#pragma unroll
    for (int mi = 0; mi < 4; mi++) {
#pragma unroll
        for (int nt = 0; nt < 4; nt++) {
            int pxo = xh * 64 + bn + nt * 8 + 2 * tg;
            int o0  = bo + mi * 16 + g;
            int o1  = o0 + 8;
            float* base = out + (size_t)b * OUTC * HW + y * Ww + pxo;
            *(float2*)(base + (size_t)o0 * HW) = make_float2(acc[mi][nt][0], acc[mi][nt][1]);
            *(float2*)(base + (size_t)o1 * HW) = make_float2(acc[mi][nt][2], acc[mi][nt][3]);
        }
    }
}

// ======================================================================
// launch
// ======================================================================
extern "C" void kernel_launch(void* const* d_in, const int* in_sizes, int n_in,
                              void* d_out, int out_size)
{
    const float* x  = nullptr;   // 8388608
    const float* wp = nullptr;   // 20736
    const float* bp = nullptr;   // 18
    const float* wc = nullptr;   // 294912
    for (int i = 0; i < n_in; i++) {
        switch (in_sizes[i]) {
            case 8388608: x  = (const float*)d_in[i]; break;
            case 20736:   wp = (const float*)d_in[i]; break;
            case 18:      bp = (const float*)d_in[i]; break;
            case 294912:  wc = (const float*)d_in[i]; break;
            default: break;
        }
    }
    if (!x)  x  = (const float*)d_in[0];
    if (!wp) wp = (const float*)d_in[1];
    if (!bp) bp = (const float*)d_in[2];
    if (!wc) wc = (const float*)d_in[3];

    float* out = (float*)d_out;

    cudaFuncSetAttribute(gemm_k,
                         cudaFuncAttributeMaxDynamicSharedMemorySize, G_TOTAL);

    wtrans_k<<<(NT * OUTC * BK + 255) / 256, 256>>>(wc);
    offset_conv_k<<<dim3(Hh / 2, Bb), 128>>>(x, wp, bp);
    bgen_k<<<dim3(Hh, Bb), 512>>>(x);
    gemm_k<<<dim3(2, Hh, Bb), 256, G_TOTAL>>>(out);
}

// round 12
// speedup vs baseline: 1.2753x; 1.2753x over previous
#include <cuda_runtime.h>
#include <cuda_fp16.h>
#include <cstdint>

#define Hh   128
#define Ww   128
#define HW   16384
#define Cc   128
#define NP   9
#define OUTC 256
#define Bb   4
#define BK   64
#define NT   18

typedef unsigned long long ull;
typedef unsigned int u32;

// -------- device scratch --------
__device__ float g_offset[Bb * 2 * NP * HW];            // (b, 18, H, W)
__device__ __align__(128) __half g_wa[NT * OUTC * BK];  // fp16 A tiles [tile][o][j]
__device__ __align__(128) float g_xT[(size_t)Bb * HW * Cc];  // x transposed: [b][pix][c]
// pre-swizzled fp16 B tiles: [half-job][tile] each 64px x 64k x 2B = 8192 B
__device__ __align__(128) char g_bs[(size_t)(Bb * Hh * 2) * NT * 8192];

// ---------------- helpers ----------------
__device__ __forceinline__ u32 smem_u32(const void* p) {
    u32 a;
    asm("{ .reg .u64 t; cvta.to.shared.u64 t, %1; cvt.u32.u64 %0, t; }" : "=r"(a) : "l"(p));
    return a;
}
__device__ __forceinline__ void ldsm_x4(u32& r0, u32& r1, u32& r2, u32& r3, u32 addr) {
    asm volatile("ldmatrix.sync.aligned.m8n8.x4.shared.b16 {%0,%1,%2,%3}, [%4];"
                 : "=r"(r0), "=r"(r1), "=r"(r2), "=r"(r3) : "r"(addr));
}
__device__ __forceinline__ void mma_f16(float* d, const u32* a, const u32* b) {
    asm("mma.sync.aligned.m16n8k16.row.col.f32.f16.f16.f32 "
        "{%0,%1,%2,%3},{%4,%5,%6,%7},{%8,%9},{%0,%1,%2,%3};"
        : "+f"(d[0]), "+f"(d[1]), "+f"(d[2]), "+f"(d[3])
        : "r"(a[0]), "r"(a[1]), "r"(a[2]), "r"(a[3]), "r"(b[0]), "r"(b[1]));
}
__device__ __forceinline__ u32 swz(u32 off) { return off ^ ((off >> 3) & 0x70); }

__device__ __forceinline__ void cp_async16(u32 dst, const void* src) {
    asm volatile("cp.async.cg.shared.global [%0], [%1], 16;" :: "r"(dst), "l"(src));
}
#define CP_COMMIT() asm volatile("cp.async.commit_group;" ::: "memory")
#define CP_WAIT0()  asm volatile("cp.async.wait_group 0;" ::: "memory")

// packed f32x2 helpers (offset conv)
__device__ __forceinline__ void ffma2(ull& d, ull a, ull b) {
    asm("fma.rn.f32x2 %0, %1, %2, %0;" : "+l"(d) : "l"(a), "l"(b));
}
__device__ __forceinline__ ull pack2(float lo, float hi) {
    ull r; asm("mov.b64 %0, {%1, %2};" : "=l"(r) : "f"(lo), "f"(hi)); return r;
}
__device__ __forceinline__ float2 unpack2(ull v) {
    float2 f; asm("mov.b64 {%0, %1}, %2;" : "=f"(f.x), "=f"(f.y) : "l"(v)); return f;
}

// ======================================================================
// Kernel 1: w_conv (outc, C, N, 1) -> fp16 tiled A: [tile][o][j]
// ======================================================================
__global__ void wtrans_k(const float* __restrict__ wc) {
    int i = blockIdx.x * 256 + threadIdx.x;
    if (i < NT * OUTC * BK) {
        int j = i & 63;
        int o = (i >> 6) & 255;
        int tt = i >> 14;
        int k = tt * 64 + j;
        int n = k >> 7;
        int c = k & 127;
        g_wa[i] = __float2half_rn(wc[(o * Cc + c) * NP + n]);
    }
}

// ======================================================================
// Kernel 1b: transpose x (b,C,HW) -> xT (b,HW,C)
// ======================================================================
__global__ void __launch_bounds__(256) xpose_k(const float* __restrict__ x) {
    __shared__ float tile[32][33];
    const int b  = blockIdx.z;
    const int c0 = blockIdx.y * 32;
    const int p0 = blockIdx.x * 32;
    const int tx = threadIdx.x & 31;
    const int ty = threadIdx.x >> 5;   // 0..7

    const float* xb = x + (size_t)b * Cc * HW;
#pragma unroll
    for (int i = 0; i < 32; i += 8)
        tile[ty + i][tx] = xb[(size_t)(c0 + ty + i) * HW + p0 + tx];
    __syncthreads();
    float* xTb = g_xT + (size_t)b * HW * Cc;
#pragma unroll
    for (int i = 0; i < 32; i += 8)
        xTb[(size_t)(p0 + ty + i) * Cc + c0 + tx] = tile[tx][ty + i];
}

// ======================================================================
// Kernel 2: offset conv (proven, unchanged)
// ======================================================================
__global__ void __launch_bounds__(128) offset_conv_k(
    const float* __restrict__ x,
    const float* __restrict__ wp,
    const float* __restrict__ bp)
{
    const int y0 = blockIdx.x * 2;
    const int b  = blockIdx.y;
    const int tx = threadIdx.x;

    __shared__ float xr[4][132];
    __shared__ float ws2[9][18];

    ull acc0[9], acc1[9];
#pragma unroll
    for (int p = 0; p < 9; p++) { acc0[p] = 0ULL; acc1[p] = 0ULL; }

    const float* xb = x + (size_t)b * Cc * HW;

    for (int c = 0; c < Cc; c++) {
        __syncthreads();
        for (int i = tx; i < 162; i += 128) {
            int k  = i / 18;
            int ch = i % 18;
            ws2[k][ch] = wp[ch * (Cc * 9) + c * 9 + k];
        }
        for (int i = tx; i < 4 * 132; i += 128) {
            int r  = i / 132;
            int cc = i % 132;
            int yy = y0 + r - 1;
            int xx = cc - 1;
            float v = 0.f;
            if (yy >= 0 && yy < Hh && xx >= 0 && xx < Ww)
                v = xb[c * HW + yy * Ww + xx];
            xr[r][cc] = v;
        }
        __syncthreads();

#pragma unroll
        for (int k = 0; k < 9; k++) {
            const int ky = k / 3, kx = k % 3;
            float xv0 = xr[ky][tx + kx];
            float xv1 = xr[ky + 1][tx + kx];
            ull x0d = pack2(xv0, xv0);
            ull x1d = pack2(xv1, xv1);
            const ull* wrow = (const ull*)&ws2[k][0];
#pragma unroll
            for (int p = 0; p < 9; p++) {
                ull wpair = wrow[p];
                ffma2(acc0[p], wpair, x0d);
                ffma2(acc1[p], wpair, x1d);
            }
        }
    }

#pragma unroll
    for (int p = 0; p < 9; p++) {
        float2 a0 = unpack2(acc0[p]);
        float2 a1 = unpack2(acc1[p]);
        int ch0 = 2 * p, ch1 = 2 * p + 1;
        float b0 = bp[ch0], b1 = bp[ch1];
        g_offset[((b * 18 + ch0) * Hh + y0) * Ww + tx]     = a0.x + b0;
        g_offset[((b * 18 + ch1) * Hh + y0) * Ww + tx]     = a0.y + b1;
        g_offset[((b * 18 + ch0) * Hh + y0 + 1) * Ww + tx] = a1.x + b0;
        g_offset[((b * 18 + ch1) * Hh + y0 + 1) * Ww + tx] = a1.y + b1;
    }
}

// ======================================================================
// Kernel 3: bgen v2 — coalesced gather from xT.
// Block = (y, b), 512 thr = 16 warps. Warp = one (px, n) pair at a time;
// lanes = channels (4 per lane). 4 corner LDG.128 per pair.
// ======================================================================
__global__ void __launch_bounds__(512)
bgen_k()
{
    __shared__ float4  metaw[NP * 128];
    __shared__ ushort4 metai[NP * 128];

    const int t = threadIdx.x;
    const int y = blockIdx.x;
    const int b = blockIdx.y;
    const int wid = t >> 5;
    const int lane = t & 31;

    // ---- bilinear metadata for 128 px x 9 offsets ----
    for (int task = t; task < NP * 128; task += 512) {
        int n  = task >> 7;
        int px = task & 127;
        float offr = g_offset[((b * 18 + n) * Hh + y) * Ww + px];
        float offc = g_offset[((b * 18 + NP + n) * Hh + y) * Ww + px];
        float pr = (float)y  + (float)(n / 3) + offr;
        float pc = (float)px + (float)(n % 3) + offc;

        float ltr = floorf(pr), ltc = floorf(pc);
        float rbr = ltr + 1.f,  rbc = ltc + 1.f;
        ltr = fminf(fmaxf(ltr, 0.f), 127.f);
        rbr = fminf(fmaxf(rbr, 0.f), 127.f);
        ltc = fminf(fmaxf(ltc, 0.f), 127.f);
        rbc = fminf(fmaxf(rbc, 0.f), 127.f);
        pr  = fminf(fmaxf(pr, 0.f), 127.f);
        pc  = fminf(fmaxf(pc, 0.f), 127.f);

        float dr_lt = 1.f + (ltr - pr);
        float dr_rb = 1.f - (rbr - pr);
        float dc_lt = 1.f + (ltc - pc);
        float dc_rb = 1.f - (rbc - pc);

        float4 g;
        g.x = dr_lt * dc_lt;
        g.y = dr_rb * dc_rb;
        g.z = dr_lt * dc_rb;
        g.w = dr_rb * dc_lt;
        metaw[task] = g;

        int iltr = (int)ltr, iltc = (int)ltc;
        int irbr = (int)rbr, irbc = (int)rbc;
        ushort4 iv;
        iv.x = (unsigned short)(iltr * Ww + iltc);
        iv.y = (unsigned short)(irbr * Ww + irbc);
        iv.z = (unsigned short)(iltr * Ww + irbc);
        iv.w = (unsigned short)(irbr * Ww + iltc);
        metai[task] = iv;
    }
    __syncthreads();

    const float* xTb = g_xT + (size_t)b * HW * Cc;
    const int c0 = lane * 4;
    char* jbase = g_bs + (size_t)((b * Hh + y) * 2) * NT * 8192;
    const int tsub = lane >> 4;          // which of the 2 tiles this lane feeds
    const u32 colb = (u32)((c0 & 63) * 2);

    // 1152 pairs / 16 warps = 72 per warp
#pragma unroll 2
    for (int i = 0; i < 72; i++) {
        const int pair = wid * 72 + i;
        const int n  = pair >> 7;
        const int px = pair & 127;
        float4  gw = metaw[pair];
        ushort4 gi = metai[pair];

        float4 A = __ldg((const float4*)(xTb + (size_t)gi.x * Cc + c0));
        float4 B = __ldg((const float4*)(xTb + (size_t)gi.y * Cc + c0));
        float4 C = __ldg((const float4*)(xTb + (size_t)gi.z * Cc + c0));
        float4 D = __ldg((const float4*)(xTb + (size_t)gi.w * Cc + c0));

        float v0 = gw.x * A.x + gw.y * B.x + gw.z * C.x + gw.w * D.x;
        float v1 = gw.x * A.y + gw.y * B.y + gw.z * C.y + gw.w * D.y;
        float v2 = gw.x * A.z + gw.y * B.z + gw.z * C.z + gw.w * D.z;
        float v3 = gw.x * A.w + gw.y * B.w + gw.z * C.w + gw.w * D.w;

        u32 p0, p1;
        asm("cvt.rn.f16x2.f32 %0, %1, %2;" : "=r"(p0) : "f"(v1), "f"(v0));
        asm("cvt.rn.f16x2.f32 %0, %1, %2;" : "=r"(p1) : "f"(v3), "f"(v2));

        const int half = px >> 6;
        const int pxl  = px & 63;
        char* d = jbase + (size_t)(half * NT + 2 * n + tsub) * 8192;
        *(uint2*)(d + swz((u32)(pxl * 128) + colb)) = make_uint2(p0, p1);
    }
}

// ======================================================================
// Kernel 4: pure fp16 GEMM from scratch tiles. CTA = (xhalf, y, b):
// out[b, 0..255, y, xh*64 .. +63]; 256 thr = 8 warps, warp 64x32.
// ======================================================================
#define G_BUFSZ 40960           // A 32768 | B 8192
#define G_BH    32768
#define G_TOTAL (2 * G_BUFSZ)   // 81920

__global__ void __launch_bounds__(256, 2)
gemm_k(float* __restrict__ out)
{
    extern __shared__ char smem[];
    const u32 sb = smem_u32(smem);
    const int t = threadIdx.x;
    const int wid = t >> 5;
    const int lane = t & 31;
    const int xh = blockIdx.x;
    const int y = blockIdx.y;
    const int b = blockIdx.z;

    const char* bsrc = g_bs + (size_t)(((b * Hh + y) * 2 + xh) * NT) * 8192;

    float acc[4][4][4];
#pragma unroll
    for (int i = 0; i < 4; i++)
#pragma unroll
        for (int j = 0; j < 4; j++)
#pragma unroll
            for (int q = 0; q < 4; q++) acc[i][j][q] = 0.f;

    const int bo = (wid & 3) * 64;
    const int bn = (wid >> 2) * 32;

    auto fill_async = [&](int tile) {
        const u32 dst = sb + (u32)(tile & 1) * G_BUFSZ;
        const uint4* srcA = (const uint4*)(g_wa + (size_t)tile * OUTC * BK);
        const uint4* srcB = (const uint4*)(bsrc + (size_t)tile * 8192);
#pragma unroll
        for (int i = 0; i < 8; i++) {
            int e = t + i * 256;
            cp_async16(dst + swz((u32)(e * 16)), srcA + e);
        }
#pragma unroll
        for (int i = 0; i < 2; i++) {
            int e = t + i * 256;
            cp_async16(dst + G_BH + (u32)(e * 16), srcB + e);   // already swizzled
        }
        CP_COMMIT();
    };

    auto compute = [&](int tile) {
        const u32 buf  = sb + (u32)(tile & 1) * G_BUFSZ;
        const u32 bufB = buf + G_BH;
        u32 a[4][4], bf[4][2];
#pragma unroll
        for (int ks = 0; ks < 4; ks++) {
#pragma unroll
            for (int j = 0; j < 2; j++) {
                int nrow = bn + j * 16 + (lane & 7) + ((lane >> 4) << 3);
                int kb   = ks * 32 + ((lane >> 3) & 1) * 16;
                u32 sw = swz((u32)(nrow * 128 + kb));
                ldsm_x4(bf[2*j][0], bf[2*j][1], bf[2*j+1][0], bf[2*j+1][1], bufB + sw);
            }
#pragma unroll
            for (int mi = 0; mi < 4; mi++) {
                int ar = bo + mi * 16 + (lane & 15);
                int kb = ks * 32 + (lane >> 4) * 16;
                u32 sw = swz((u32)(ar * 128 + kb));
                ldsm_x4(a[mi][0], a[mi][1], a[mi][2], a[mi][3], buf + sw);
            }
#pragma unroll
            for (int mi = 0; mi < 4; mi++)
#pragma unroll
                for (int nt = 0; nt < 4; nt++)
                    mma_f16(acc[mi][nt], a[mi], bf[nt]);
        }
    };

    fill_async(0);
    CP_WAIT0();
    __syncthreads();
    for (int tile = 0; tile < NT; tile++) {
        if (tile + 1 < NT) fill_async(tile + 1);
        compute(tile);
        CP_WAIT0();
        __syncthreads();
    }

    const int g  = lane >> 2;
    const int tg = lane & 3;
#pragma unroll
    for (int mi = 0; mi < 4; mi++) {
#pragma unroll
        for (int nt = 0; nt < 4; nt++) {
            int pxo = xh * 64 + bn + nt * 8 + 2 * tg;
            int o0  = bo + mi * 16 + g;
            int o1  = o0 + 8;
            float* base = out + (size_t)b * OUTC * HW + y * Ww + pxo;
            *(float2*)(base + (size_t)o0 * HW) = make_float2(acc[mi][nt][0], acc[mi][nt][1]);
            *(float2*)(base + (size_t)o1 * HW) = make_float2(acc[mi][nt][2], acc[mi][nt][3]);
        }
    }
}

// ======================================================================
// launch
// ======================================================================
extern "C" void kernel_launch(void* const* d_in, const int* in_sizes, int n_in,
                              void* d_out, int out_size)
{
    const float* x  = nullptr;   // 8388608
    const float* wp = nullptr;   // 20736
    const float* bp = nullptr;   // 18
    const float* wc = nullptr;   // 294912
    for (int i = 0; i < n_in; i++) {
        switch (in_sizes[i]) {
            case 8388608: x  = (const float*)d_in[i]; break;
            case 20736:   wp = (const float*)d_in[i]; break;
            case 18:      bp = (const float*)d_in[i]; break;
            case 294912:  wc = (const float*)d_in[i]; break;
            default: break;
        }
    }
    if (!x)  x  = (const float*)d_in[0];
    if (!wp) wp = (const float*)d_in[1];
    if (!bp) bp = (const float*)d_in[2];
    if (!wc) wc = (const float*)d_in[3];

    float* out = (float*)d_out;

    cudaFuncSetAttribute(gemm_k,
                         cudaFuncAttributeMaxDynamicSharedMemorySize, G_TOTAL);

    wtrans_k<<<(NT * OUTC * BK + 255) / 256, 256>>>(wc);
    xpose_k<<<dim3(HW / 32, Cc / 32, Bb), 256>>>(x);
    offset_conv_k<<<dim3(Hh / 2, Bb), 128>>>(x, wp, bp);
    bgen_k<<<dim3(Hh, Bb), 512>>>();
    gemm_k<<<dim3(2, Hh, Bb), 256, G_TOTAL>>>(out);
}

// round 13
// speedup vs baseline: 1.4789x; 1.1597x over previous
#include <cuda_runtime.h>
#include <cuda_fp16.h>
#include <cstdint>

#define Hh   128
#define Ww   128
#define HW   16384
#define Cc   128
#define NP   9
#define OUTC 256
#define Bb   4
#define BK   64
#define NT   18

typedef unsigned long long ull;
typedef unsigned int u32;

// -------- device scratch --------
__device__ float g_offset[Bb * 2 * NP * HW];            // (b, 18, H, W)
__device__ __align__(128) __half g_wa[NT * OUTC * BK];  // fp16 A tiles [tile][o][j]
__device__ __align__(128) float g_xT[(size_t)Bb * HW * Cc];  // x transposed: [b][pix][c]
// pre-swizzled fp16 B tiles: [half-job][tile] each 64px x 64k x 2B = 8192 B
__device__ __align__(128) char g_bs[(size_t)(Bb * Hh * 2) * NT * 8192];

// ---------------- helpers ----------------
__device__ __forceinline__ u32 smem_u32(const void* p) {
    u32 a;
    asm("{ .reg .u64 t; cvta.to.shared.u64 t, %1; cvt.u32.u64 %0, t; }" : "=r"(a) : "l"(p));
    return a;
}
__device__ __forceinline__ void ldsm_x4(u32& r0, u32& r1, u32& r2, u32& r3, u32 addr) {
    asm volatile("ldmatrix.sync.aligned.m8n8.x4.shared.b16 {%0,%1,%2,%3}, [%4];"
                 : "=r"(r0), "=r"(r1), "=r"(r2), "=r"(r3) : "r"(addr));
}
__device__ __forceinline__ void mma_f16(float* d, const u32* a, const u32* b) {
    asm("mma.sync.aligned.m16n8k16.row.col.f32.f16.f16.f32 "
        "{%0,%1,%2,%3},{%4,%5,%6,%7},{%8,%9},{%0,%1,%2,%3};"
        : "+f"(d[0]), "+f"(d[1]), "+f"(d[2]), "+f"(d[3])
        : "r"(a[0]), "r"(a[1]), "r"(a[2]), "r"(a[3]), "r"(b[0]), "r"(b[1]));
}
__device__ __forceinline__ u32 swz(u32 off) { return off ^ ((off >> 3) & 0x70); }

__device__ __forceinline__ void cp_async16(u32 dst, const void* src) {
    asm volatile("cp.async.cg.shared.global [%0], [%1], 16;" :: "r"(dst), "l"(src));
}
#define CP_COMMIT() asm volatile("cp.async.commit_group;" ::: "memory")
#define CP_WAIT0()  asm volatile("cp.async.wait_group 0;" ::: "memory")

// packed f32x2 helpers (offset conv)
__device__ __forceinline__ void ffma2(ull& d, ull a, ull b) {
    asm("fma.rn.f32x2 %0, %1, %2, %0;" : "+l"(d) : "l"(a), "l"(b));
}
__device__ __forceinline__ ull pack2(float lo, float hi) {
    ull r; asm("mov.b64 %0, {%1, %2};" : "=l"(r) : "f"(lo), "f"(hi)); return r;
}
__device__ __forceinline__ float2 unpack2(ull v) {
    float2 f; asm("mov.b64 {%0, %1}, %2;" : "=f"(f.x), "=f"(f.y) : "l"(v)); return f;
}

// ======================================================================
// Kernel 1: w_conv (outc, C, N, 1) -> fp16 tiled A: [tile][o][j]
// ======================================================================
__global__ void wtrans_k(const float* __restrict__ wc) {
    int i = blockIdx.x * 256 + threadIdx.x;
    if (i < NT * OUTC * BK) {
        int j = i & 63;
        int o = (i >> 6) & 255;
        int tt = i >> 14;
        int k = tt * 64 + j;
        int n = k >> 7;
        int c = k & 127;
        g_wa[i] = __float2half_rn(wc[(o * Cc + c) * NP + n]);
    }
}

// ======================================================================
// Kernel 1b: transpose x (b,C,HW) -> xT (b,HW,C)
// ======================================================================
__global__ void __launch_bounds__(256) xpose_k(const float* __restrict__ x) {
    __shared__ float tile[32][33];
    const int b  = blockIdx.z;
    const int c0 = blockIdx.y * 32;
    const int p0 = blockIdx.x * 32;
    const int tx = threadIdx.x & 31;
    const int ty = threadIdx.x >> 5;   // 0..7

    const float* xb = x + (size_t)b * Cc * HW;
#pragma unroll
    for (int i = 0; i < 32; i += 8)
        tile[ty + i][tx] = xb[(size_t)(c0 + ty + i) * HW + p0 + tx];
    __syncthreads();
    float* xTb = g_xT + (size_t)b * HW * Cc;
#pragma unroll
    for (int i = 0; i < 32; i += 8)
        xTb[(size_t)(p0 + ty + i) * Cc + c0 + tx] = tile[tx][ty + i];
}

// ======================================================================
// Kernel 2: offset conv v2 — 256 thr (2 rows x 128 px), double-buffered
// smem, ONE barrier per channel. Thread: one row, all 18 channels.
// ======================================================================
__global__ void __launch_bounds__(256) offset_conv_k(
    const float* __restrict__ x,
    const float* __restrict__ wp,
    const float* __restrict__ bp)
{
    const int y0  = blockIdx.x * 2;
    const int b   = blockIdx.y;
    const int t   = threadIdx.x;
    const int row = t >> 7;          // 0/1
    const int px  = t & 127;

    __shared__ float xr[2][4][132];  // [buf][row y0-1..y0+2][col -1..130]
    __shared__ float ws2[2][9][18];  // [buf][tap][channel]

    ull acc[9];
#pragma unroll
    for (int p = 0; p < 9; p++) acc[p] = 0ULL;

    const float* xb = x + (size_t)b * Cc * HW;

    auto load_ch = [&](int c, int s) {
        // weights: 162 floats; x rows: 4*132 = 528 floats
        for (int i = t; i < 162; i += 256) {
            int k  = i / 18;
            int ch = i % 18;
            ws2[s][k][ch] = wp[ch * (Cc * 9) + c * 9 + k];
        }
        for (int i = t; i < 528; i += 256) {
            int r  = i / 132;
            int cc = i % 132;
            int yy = y0 + r - 1;
            int xx = cc - 1;
            float v = 0.f;
            if (yy >= 0 && yy < Hh && xx >= 0 && xx < Ww)
                v = xb[c * HW + yy * Ww + xx];
            xr[s][r][cc] = v;
        }
    };

    load_ch(0, 0);
    __syncthreads();

    for (int c = 0; c < Cc; c++) {
        const int s = c & 1;
        if (c + 1 < Cc) load_ch(c + 1, s ^ 1);

#pragma unroll
        for (int k = 0; k < 9; k++) {
            const int ky = k / 3, kx = k % 3;
            float xv = xr[s][row + ky][px + kx];
            ull xd = pack2(xv, xv);
            const ull* wrow = (const ull*)&ws2[s][k][0];
#pragma unroll
            for (int p = 0; p < 9; p++)
                ffma2(acc[p], wrow[p], xd);
        }
        __syncthreads();
    }

#pragma unroll
    for (int p = 0; p < 9; p++) {
        float2 a = unpack2(acc[p]);
        int ch0 = 2 * p, ch1 = 2 * p + 1;
        g_offset[((b * 18 + ch0) * Hh + y0 + row) * Ww + px] = a.x + bp[ch0];
        g_offset[((b * 18 + ch1) * Hh + y0 + row) * Ww + px] = a.y + bp[ch1];
    }
}

// ======================================================================
// Kernel 3: bgen v2 — coalesced gather from xT (proven, unchanged)
// ======================================================================
__global__ void __launch_bounds__(512)
bgen_k()
{
    __shared__ float4  metaw[NP * 128];
    __shared__ ushort4 metai[NP * 128];

    const int t = threadIdx.x;
    const int y = blockIdx.x;
    const int b = blockIdx.y;
    const int wid = t >> 5;
    const int lane = t & 31;

    for (int task = t; task < NP * 128; task += 512) {
        int n  = task >> 7;
        int px = task & 127;
        float offr = g_offset[((b * 18 + n) * Hh + y) * Ww + px];
        float offc = g_offset[((b * 18 + NP + n) * Hh + y) * Ww + px];
        float pr = (float)y  + (float)(n / 3) + offr;
        float pc = (float)px + (float)(n % 3) + offc;

        float ltr = floorf(pr), ltc = floorf(pc);
        float rbr = ltr + 1.f,  rbc = ltc + 1.f;
        ltr = fminf(fmaxf(ltr, 0.f), 127.f);
        rbr = fminf(fmaxf(rbr, 0.f), 127.f);
        ltc = fminf(fmaxf(ltc, 0.f), 127.f);
        rbc = fminf(fmaxf(rbc, 0.f), 127.f);
        pr  = fminf(fmaxf(pr, 0.f), 127.f);
        pc  = fminf(fmaxf(pc, 0.f), 127.f);

        float dr_lt = 1.f + (ltr - pr);
        float dr_rb = 1.f - (rbr - pr);
        float dc_lt = 1.f + (ltc - pc);
        float dc_rb = 1.f - (rbc - pc);

        float4 g;
        g.x = dr_lt * dc_lt;
        g.y = dr_rb * dc_rb;
        g.z = dr_lt * dc_rb;
        g.w = dr_rb * dc_lt;
        metaw[task] = g;

        int iltr = (int)ltr, iltc = (int)ltc;
        int irbr = (int)rbr, irbc = (int)rbc;
        ushort4 iv;
        iv.x = (unsigned short)(iltr * Ww + iltc);
        iv.y = (unsigned short)(irbr * Ww + irbc);
        iv.z = (unsigned short)(iltr * Ww + irbc);
        iv.w = (unsigned short)(irbr * Ww + iltc);
        metai[task] = iv;
    }
    __syncthreads();

    const float* xTb = g_xT + (size_t)b * HW * Cc;
    const int c0 = lane * 4;
    char* jbase = g_bs + (size_t)((b * Hh + y) * 2) * NT * 8192;
    const int tsub = lane >> 4;
    const u32 colb = (u32)((c0 & 63) * 2);

#pragma unroll 2
    for (int i = 0; i < 72; i++) {
        const int pair = wid * 72 + i;
        const int n  = pair >> 7;
        const int px = pair & 127;
        float4  gw = metaw[pair];
        ushort4 gi = metai[pair];

        float4 A = __ldg((const float4*)(xTb + (size_t)gi.x * Cc + c0));
        float4 B = __ldg((const float4*)(xTb + (size_t)gi.y * Cc + c0));
        float4 C = __ldg((const float4*)(xTb + (size_t)gi.z * Cc + c0));
        float4 D = __ldg((const float4*)(xTb + (size_t)gi.w * Cc + c0));

        float v0 = gw.x * A.x + gw.y * B.x + gw.z * C.x + gw.w * D.x;
        float v1 = gw.x * A.y + gw.y * B.y + gw.z * C.y + gw.w * D.y;
        float v2 = gw.x * A.z + gw.y * B.z + gw.z * C.z + gw.w * D.z;
        float v3 = gw.x * A.w + gw.y * B.w + gw.z * C.w + gw.w * D.w;

        u32 p0, p1;
        asm("cvt.rn.f16x2.f32 %0, %1, %2;" : "=r"(p0) : "f"(v1), "f"(v0));
        asm("cvt.rn.f16x2.f32 %0, %1, %2;" : "=r"(p1) : "f"(v3), "f"(v2));

        const int half = px >> 6;
        const int pxl  = px & 63;
        char* d = jbase + (size_t)(half * NT + 2 * n + tsub) * 8192;
        *(uint2*)(d + swz((u32)(pxl * 128) + colb)) = make_uint2(p0, p1);
    }
}

// ======================================================================
// Kernel 4: pure fp16 GEMM from scratch tiles (proven, unchanged)
// ======================================================================
#define G_BUFSZ 40960           // A 32768 | B 8192
#define G_BH    32768
#define G_TOTAL (2 * G_BUFSZ)   // 81920

__global__ void __launch_bounds__(256, 2)
gemm_k(float* __restrict__ out)
{
    extern __shared__ char smem[];
    const u32 sb = smem_u32(smem);
    const int t = threadIdx.x;
    const int wid = t >> 5;
    const int lane = t & 31;
    const int xh = blockIdx.x;
    const int y = blockIdx.y;
    const int b = blockIdx.z;

    const char* bsrc = g_bs + (size_t)(((b * Hh + y) * 2 + xh) * NT) * 8192;

    float acc[4][4][4];
#pragma unroll
    for (int i = 0; i < 4; i++)
#pragma unroll
        for (int j = 0; j < 4; j++)
#pragma unroll
            for (int q = 0; q < 4; q++) acc[i][j][q] = 0.f;

    const int bo = (wid & 3) * 64;
    const int bn = (wid >> 2) * 32;

    auto fill_async = [&](int tile) {
        const u32 dst = sb + (u32)(tile & 1) * G_BUFSZ;
        const uint4* srcA = (const uint4*)(g_wa + (size_t)tile * OUTC * BK);
        const uint4* srcB = (const uint4*)(bsrc + (size_t)tile * 8192);
#pragma unroll
        for (int i = 0; i < 8; i++) {
            int e = t + i * 256;
            cp_async16(dst + swz((u32)(e * 16)), srcA + e);
        }
#pragma unroll
        for (int i = 0; i < 2; i++) {
            int e = t + i * 256;
            cp_async16(dst + G_BH + (u32)(e * 16), srcB + e);   // already swizzled
        }
        CP_COMMIT();
    };

    auto compute = [&](int tile) {
        const u32 buf  = sb + (u32)(tile & 1) * G_BUFSZ;
        const u32 bufB = buf + G_BH;
        u32 a[4][4], bf[4][2];
#pragma unroll
        for (int ks = 0; ks < 4; ks++) {
#pragma unroll
            for (int j = 0; j < 2; j++) {
                int nrow = bn + j * 16 + (lane & 7) + ((lane >> 4) << 3);
                int kb   = ks * 32 + ((lane >> 3) & 1) * 16;
                u32 sw = swz((u32)(nrow * 128 + kb));
                ldsm_x4(bf[2*j][0], bf[2*j][1], bf[2*j+1][0], bf[2*j+1][1], bufB + sw);
            }
#pragma unroll
            for (int mi = 0; mi < 4; mi++) {
                int ar = bo + mi * 16 + (lane & 15);
                int kb = ks * 32 + (lane >> 4) * 16;
                u32 sw = swz((u32)(ar * 128 + kb));
                ldsm_x4(a[mi][0], a[mi][1], a[mi][2], a[mi][3], buf + sw);
            }
#pragma unroll
            for (int mi = 0; mi < 4; mi++)
#pragma unroll
                for (int nt = 0; nt < 4; nt++)
                    mma_f16(acc[mi][nt], a[mi], bf[nt]);
        }
    };

    fill_async(0);
    CP_WAIT0();
    __syncthreads();
    for (int tile = 0; tile < NT; tile++) {
        if (tile + 1 < NT) fill_async(tile + 1);
        compute(tile);
        CP_WAIT0();
        __syncthreads();
    }

    const int g  = lane >> 2;
    const int tg = lane & 3;
#pragma unroll
    for (int mi = 0; mi < 4; mi++) {
#pragma unroll
        for (int nt = 0; nt < 4; nt++) {
            int pxo = xh * 64 + bn + nt * 8 + 2 * tg;
            int o0  = bo + mi * 16 + g;
            int o1  = o0 + 8;
            float* base = out + (size_t)b * OUTC * HW + y * Ww + pxo;
            *(float2*)(base + (size_t)o0 * HW) = make_float2(acc[mi][nt][0], acc[mi][nt][1]);
            *(float2*)(base + (size_t)o1 * HW) = make_float2(acc[mi][nt][2], acc[mi][nt][3]);
        }
    }
}

// ======================================================================
// launch
// ======================================================================
extern "C" void kernel_launch(void* const* d_in, const int* in_sizes, int n_in,
                              void* d_out, int out_size)
{
    const float* x  = nullptr;   // 8388608
    const float* wp = nullptr;   // 20736
    const float* bp = nullptr;   // 18
    const float* wc = nullptr;   // 294912
    for (int i = 0; i < n_in; i++) {
        switch (in_sizes[i]) {
            case 8388608: x  = (const float*)d_in[i]; break;
            case 20736:   wp = (const float*)d_in[i]; break;
            case 18:      bp = (const float*)d_in[i]; break;
            case 294912:  wc = (const float*)d_in[i]; break;
            default: break;
        }
    }
    if (!x)  x  = (const float*)d_in[0];
    if (!wp) wp = (const float*)d_in[1];
    if (!bp) bp = (const float*)d_in[2];
    if (!wc) wc = (const float*)d_in[3];

    float* out = (float*)d_out;

    cudaFuncSetAttribute(gemm_k,
                         cudaFuncAttributeMaxDynamicSharedMemorySize, G_TOTAL);

    wtrans_k<<<(NT * OUTC * BK + 255) / 256, 256>>>(wc);
    xpose_k<<<dim3(HW / 32, Cc / 32, Bb), 256>>>(x);
    offset_conv_k<<<dim3(Hh / 2, Bb), 256>>>(x, wp, bp);
    bgen_k<<<dim3(Hh, Bb), 512>>>();
    gemm_k<<<dim3(2, Hh, Bb), 256, G_TOTAL>>>(out);
}

// round 14
// speedup vs baseline: 1.6175x; 1.0937x over previous
#include <cuda_runtime.h>
#include <cuda_fp16.h>
#include <cstdint>

#define Hh   128
#define Ww   128
#define HW   16384
#define Cc   128
#define NP   9
#define OUTC 256
#define Bb   4
#define BK   64
#define NT   18

typedef unsigned long long ull;
typedef unsigned int u32;

// -------- device scratch --------
// 4-way channel-split partial offsets: [cg][b][18][HW]
__device__ float g_offp[4 * Bb * 2 * NP * HW];
__device__ __align__(128) __half g_wa[NT * OUTC * BK];  // fp16 A tiles [tile][o][j]
__device__ __align__(128) float g_xT[(size_t)Bb * HW * Cc];  // x transposed: [b][pix][c]
// pre-swizzled fp16 B tiles: [half-job][tile] each 64px x 64k x 2B = 8192 B
__device__ __align__(128) char g_bs[(size_t)(Bb * Hh * 2) * NT * 8192];

// ---------------- helpers ----------------
__device__ __forceinline__ u32 smem_u32(const void* p) {
    u32 a;
    asm("{ .reg .u64 t; cvta.to.shared.u64 t, %1; cvt.u32.u64 %0, t; }" : "=r"(a) : "l"(p));
    return a;
}
__device__ __forceinline__ void ldsm_x4(u32& r0, u32& r1, u32& r2, u32& r3, u32 addr) {
    asm volatile("ldmatrix.sync.aligned.m8n8.x4.shared.b16 {%0,%1,%2,%3}, [%4];"
                 : "=r"(r0), "=r"(r1), "=r"(r2), "=r"(r3) : "r"(addr));
}
__device__ __forceinline__ void mma_f16(float* d, const u32* a, const u32* b) {
    asm("mma.sync.aligned.m16n8k16.row.col.f32.f16.f16.f32 "
        "{%0,%1,%2,%3},{%4,%5,%6,%7},{%8,%9},{%0,%1,%2,%3};"
        : "+f"(d[0]), "+f"(d[1]), "+f"(d[2]), "+f"(d[3])
        : "r"(a[0]), "r"(a[1]), "r"(a[2]), "r"(a[3]), "r"(b[0]), "r"(b[1]));
}
__device__ __forceinline__ u32 swz(u32 off) { return off ^ ((off >> 3) & 0x70); }

__device__ __forceinline__ void cp_async16(u32 dst, const void* src) {
    asm volatile("cp.async.cg.shared.global [%0], [%1], 16;" :: "r"(dst), "l"(src));
}
#define CP_COMMIT() asm volatile("cp.async.commit_group;" ::: "memory")
#define CP_WAIT0()  asm volatile("cp.async.wait_group 0;" ::: "memory")

// packed f32x2 helpers (offset conv)
__device__ __forceinline__ void ffma2(ull& d, ull a, ull b) {
    asm("fma.rn.f32x2 %0, %1, %2, %0;" : "+l"(d) : "l"(a), "l"(b));
}
__device__ __forceinline__ ull pack2(float lo, float hi) {
    ull r; asm("mov.b64 %0, {%1, %2};" : "=l"(r) : "f"(lo), "f"(hi)); return r;
}
__device__ __forceinline__ float2 unpack2(ull v) {
    float2 f; asm("mov.b64 {%0, %1}, %2;" : "=f"(f.x), "=f"(f.y) : "l"(v)); return f;
}

// ======================================================================
// Kernel 1: w_conv (outc, C, N, 1) -> fp16 tiled A: [tile][o][j]
// ======================================================================
__global__ void wtrans_k(const float* __restrict__ wc) {
    int i = blockIdx.x * 256 + threadIdx.x;
    if (i < NT * OUTC * BK) {
        int j = i & 63;
        int o = (i >> 6) & 255;
        int tt = i >> 14;
        int k = tt * 64 + j;
        int n = k >> 7;
        int c = k & 127;
        g_wa[i] = __float2half_rn(wc[(o * Cc + c) * NP + n]);
    }
}

// ======================================================================
// Kernel 1b: transpose x (b,C,HW) -> xT (b,HW,C)
// ======================================================================
__global__ void __launch_bounds__(256) xpose_k(const float* __restrict__ x) {
    __shared__ float tile[32][33];
    const int b  = blockIdx.z;
    const int c0 = blockIdx.y * 32;
    const int p0 = blockIdx.x * 32;
    const int tx = threadIdx.x & 31;
    const int ty = threadIdx.x >> 5;   // 0..7

    const float* xb = x + (size_t)b * Cc * HW;
#pragma unroll
    for (int i = 0; i < 32; i += 8)
        tile[ty + i][tx] = xb[(size_t)(c0 + ty + i) * HW + p0 + tx];
    __syncthreads();
    float* xTb = g_xT + (size_t)b * HW * Cc;
#pragma unroll
    for (int i = 0; i < 32; i += 8)
        xTb[(size_t)(p0 + ty + i) * Cc + c0 + tx] = tile[tx][ty + i];
}

// ======================================================================
// Kernel 2: offset conv v3 — 4-way channel split for occupancy.
// Grid (row-pair, ch-group, batch) = (64, 4, 4); 256 thr; each CTA
// reduces 32 input channels into its private partial buffer.
// ======================================================================
__global__ void __launch_bounds__(256) offset_conv_k(
    const float* __restrict__ x,
    const float* __restrict__ wp)
{
    const int y0  = blockIdx.x * 2;
    const int cg  = blockIdx.y;      // channel group 0..3
    const int b   = blockIdx.z;
    const int t   = threadIdx.x;
    const int row = t >> 7;          // 0/1
    const int px  = t & 127;
    const int cbase = cg * 32;

    __shared__ float xr[2][4][132];  // [buf][row y0-1..y0+2][col -1..130]
    __shared__ float ws2[2][9][18];  // [buf][tap][channel]

    ull acc[9];
#pragma unroll
    for (int p = 0; p < 9; p++) acc[p] = 0ULL;

    const float* xb = x + (size_t)b * Cc * HW;

    auto load_ch = [&](int ci, int s) {
        const int c = cbase + ci;
        for (int i = t; i < 162; i += 256) {
            int k  = i / 18;
            int ch = i % 18;
            ws2[s][k][ch] = wp[ch * (Cc * 9) + c * 9 + k];
        }
        for (int i = t; i < 528; i += 256) {
            int r  = i / 132;
            int cc = i % 132;
            int yy = y0 + r - 1;
            int xx = cc - 1;
            float v = 0.f;
            if (yy >= 0 && yy < Hh && xx >= 0 && xx < Ww)
                v = xb[c * HW + yy * Ww + xx];
            xr[s][r][cc] = v;
        }
    };

    load_ch(0, 0);
    __syncthreads();

    for (int ci = 0; ci < 32; ci++) {
        const int s = ci & 1;
        if (ci + 1 < 32) load_ch(ci + 1, s ^ 1);

#pragma unroll
        for (int k = 0; k < 9; k++) {
            const int ky = k / 3, kx = k % 3;
            float xv = xr[s][row + ky][px + kx];
            ull xd = pack2(xv, xv);
            const ull* wrow = (const ull*)&ws2[s][k][0];
#pragma unroll
            for (int p = 0; p < 9; p++)
                ffma2(acc[p], wrow[p], xd);
        }
        __syncthreads();
    }

    float* P = g_offp + (size_t)((cg * Bb + b) * 18) * HW;
#pragma unroll
    for (int p = 0; p < 9; p++) {
        float2 a = unpack2(acc[p]);
        P[(2 * p)     * HW + (y0 + row) * Ww + px] = a.x;
        P[(2 * p + 1) * HW + (y0 + row) * Ww + px] = a.y;
    }
}

// ======================================================================
// Kernel 3: bgen v2 — sums the 4 offset partials + bias in prologue,
// then coalesced gather from xT (proven).
// ======================================================================
__global__ void __launch_bounds__(512)
bgen_k(const float* __restrict__ bp)
{
    __shared__ float4  metaw[NP * 128];
    __shared__ ushort4 metai[NP * 128];

    const int t = threadIdx.x;
    const int y = blockIdx.x;
    const int b = blockIdx.y;
    const int wid = t >> 5;
    const int lane = t & 31;

    for (int task = t; task < NP * 128; task += 512) {
        int n  = task >> 7;
        int px = task & 127;
        float offr = bp[n];
        float offc = bp[NP + n];
#pragma unroll
        for (int cg = 0; cg < 4; cg++) {
            const float* P = g_offp + (size_t)((cg * Bb + b) * 18) * HW;
            offr += P[n * HW + y * Ww + px];
            offc += P[(NP + n) * HW + y * Ww + px];
        }
        float pr = (float)y  + (float)(n / 3) + offr;
        float pc = (float)px + (float)(n % 3) + offc;

        float ltr = floorf(pr), ltc = floorf(pc);
        float rbr = ltr + 1.f,  rbc = ltc + 1.f;
        ltr = fminf(fmaxf(ltr, 0.f), 127.f);
        rbr = fminf(fmaxf(rbr, 0.f), 127.f);
        ltc = fminf(fmaxf(ltc, 0.f), 127.f);
        rbc = fminf(fmaxf(rbc, 0.f), 127.f);
        pr  = fminf(fmaxf(pr, 0.f), 127.f);
        pc  = fminf(fmaxf(pc, 0.f), 127.f);

        float dr_lt = 1.f + (ltr - pr);
        float dr_rb = 1.f - (rbr - pr);
        float dc_lt = 1.f + (ltc - pc);
        float dc_rb = 1.f - (rbc - pc);

        float4 g;
        g.x = dr_lt * dc_lt;
        g.y = dr_rb * dc_rb;
        g.z = dr_lt * dc_rb;
        g.w = dr_rb * dc_lt;
        metaw[task] = g;

        int iltr = (int)ltr, iltc = (int)ltc;
        int irbr = (int)rbr, irbc = (int)rbc;
        ushort4 iv;
        iv.x = (unsigned short)(iltr * Ww + iltc);
        iv.y = (unsigned short)(irbr * Ww + irbc);
        iv.z = (unsigned short)(iltr * Ww + irbc);
        iv.w = (unsigned short)(irbr * Ww + iltc);
        metai[task] = iv;
    }
    __syncthreads();

    const float* xTb = g_xT + (size_t)b * HW * Cc;
    const int c0 = lane * 4;
    char* jbase = g_bs + (size_t)((b * Hh + y) * 2) * NT * 8192;
    const int tsub = lane >> 4;
    const u32 colb = (u32)((c0 & 63) * 2);

#pragma unroll 2
    for (int i = 0; i < 72; i++) {
        const int pair = wid * 72 + i;
        const int n  = pair >> 7;
        const int px = pair & 127;
        float4  gw = metaw[pair];
        ushort4 gi = metai[pair];

        float4 A = __ldg((const float4*)(xTb + (size_t)gi.x * Cc + c0));
        float4 B = __ldg((const float4*)(xTb + (size_t)gi.y * Cc + c0));
        float4 C = __ldg((const float4*)(xTb + (size_t)gi.z * Cc + c0));
        float4 D = __ldg((const float4*)(xTb + (size_t)gi.w * Cc + c0));

        float v0 = gw.x * A.x + gw.y * B.x + gw.z * C.x + gw.w * D.x;
        float v1 = gw.x * A.y + gw.y * B.y + gw.z * C.y + gw.w * D.y;
        float v2 = gw.x * A.z + gw.y * B.z + gw.z * C.z + gw.w * D.z;
        float v3 = gw.x * A.w + gw.y * B.w + gw.z * C.w + gw.w * D.w;

        u32 p0, p1;
        asm("cvt.rn.f16x2.f32 %0, %1, %2;" : "=r"(p0) : "f"(v1), "f"(v0));
        asm("cvt.rn.f16x2.f32 %0, %1, %2;" : "=r"(p1) : "f"(v3), "f"(v2));

        const int half = px >> 6;
        const int pxl  = px & 63;
        char* d = jbase + (size_t)(half * NT + 2 * n + tsub) * 8192;
        *(uint2*)(d + swz((u32)(pxl * 128) + colb)) = make_uint2(p0, p1);
    }
}

// ======================================================================
// Kernel 4: pure fp16 GEMM from scratch tiles (proven, unchanged)
// ======================================================================
#define G_BUFSZ 40960           // A 32768 | B 8192
#define G_BH    32768
#define G_TOTAL (2 * G_BUFSZ)   // 81920

__global__ void __launch_bounds__(256, 2)
gemm_k(float* __restrict__ out)
{
    extern __shared__ char smem[];
    const u32 sb = smem_u32(smem);
    const int t = threadIdx.x;
    const int wid = t >> 5;
    const int lane = t & 31;
    const int xh = blockIdx.x;
    const int y = blockIdx.y;
    const int b = blockIdx.z;

    const char* bsrc = g_bs + (size_t)(((b * Hh + y) * 2 + xh) * NT) * 8192;

    float acc[4][4][4];
#pragma unroll
    for (int i = 0; i < 4; i++)
#pragma unroll
        for (int j = 0; j < 4; j++)
#pragma unroll
            for (int q = 0; q < 4; q++) acc[i][j][q] = 0.f;

    const int bo = (wid & 3) * 64;
    const int bn = (wid >> 2) * 32;

    auto fill_async = [&](int tile) {
        const u32 dst = sb + (u32)(tile & 1) * G_BUFSZ;
        const uint4* srcA = (const uint4*)(g_wa + (size_t)tile * OUTC * BK);
        const uint4* srcB = (const uint4*)(bsrc + (size_t)tile * 8192);
#pragma unroll
        for (int i = 0; i < 8; i++) {
            int e = t + i * 256;
            cp_async16(dst + swz((u32)(e * 16)), srcA + e);
        }
#pragma unroll
        for (int i = 0; i < 2; i++) {
            int e = t + i * 256;
            cp_async16(dst + G_BH + (u32)(e * 16), srcB + e);   // already swizzled
        }
        CP_COMMIT();
    };

    auto compute = [&](int tile) {
        const u32 buf  = sb + (u32)(tile & 1) * G_BUFSZ;
        const u32 bufB = buf + G_BH;
        u32 a[4][4], bf[4][2];
#pragma unroll
        for (int ks = 0; ks < 4; ks++) {
#pragma unroll
            for (int j = 0; j < 2; j++) {
                int nrow = bn + j * 16 + (lane & 7) + ((lane >> 4) << 3);
                int kb   = ks * 32 + ((lane >> 3) & 1) * 16;
                u32 sw = swz((u32)(nrow * 128 + kb));
                ldsm_x4(bf[2*j][0], bf[2*j][1], bf[2*j+1][0], bf[2*j+1][1], bufB + sw);
            }
#pragma unroll
            for (int mi = 0; mi < 4; mi++) {
                int ar = bo + mi * 16 + (lane & 15);
                int kb = ks * 32 + (lane >> 4) * 16;
                u32 sw = swz((u32)(ar * 128 + kb));
                ldsm_x4(a[mi][0], a[mi][1], a[mi][2], a[mi][3], buf + sw);
            }
#pragma unroll
            for (int mi = 0; mi < 4; mi++)
#pragma unroll
                for (int nt = 0; nt < 4; nt++)
                    mma_f16(acc[mi][nt], a[mi], bf[nt]);
        }
    };

    fill_async(0);
    CP_WAIT0();
    __syncthreads();
    for (int tile = 0; tile < NT; tile++) {
        if (tile + 1 < NT) fill_async(tile + 1);
        compute(tile);
        CP_WAIT0();
        __syncthreads();
    }

    const int g  = lane >> 2;
    const int tg = lane & 3;
#pragma unroll
    for (int mi = 0; mi < 4; mi++) {
#pragma unroll
        for (int nt = 0; nt < 4; nt++) {
            int pxo = xh * 64 + bn + nt * 8 + 2 * tg;
            int o0  = bo + mi * 16 + g;
            int o1  = o0 + 8;
            float* base = out + (size_t)b * OUTC * HW + y * Ww + pxo;
            *(float2*)(base + (size_t)o0 * HW) = make_float2(acc[mi][nt][0], acc[mi][nt][1]);
            *(float2*)(base + (size_t)o1 * HW) = make_float2(acc[mi][nt][2], acc[mi][nt][3]);
        }
    }
}

// ======================================================================
// launch
// ======================================================================
extern "C" void kernel_launch(void* const* d_in, const int* in_sizes, int n_in,
                              void* d_out, int out_size)
{
    const float* x  = nullptr;   // 8388608
    const float* wp = nullptr;   // 20736
    const float* bp = nullptr;   // 18
    const float* wc = nullptr;   // 294912
    for (int i = 0; i < n_in; i++) {
        switch (in_sizes[i]) {
            case 8388608: x  = (const float*)d_in[i]; break;
            case 20736:   wp = (const float*)d_in[i]; break;
            case 18:      bp = (const float*)d_in[i]; break;
            case 294912:  wc = (const float*)d_in[i]; break;
            default: break;
        }
    }
    if (!x)  x  = (const float*)d_in[0];
    if (!wp) wp = (const float*)d_in[1];
    if (!bp) bp = (const float*)d_in[2];
    if (!wc) wc = (const float*)d_in[3];

    float* out = (float*)d_out;

    cudaFuncSetAttribute(gemm_k,
                         cudaFuncAttributeMaxDynamicSharedMemorySize, G_TOTAL);

    wtrans_k<<<(NT * OUTC * BK + 255) / 256, 256>>>(wc);
    xpose_k<<<dim3(HW / 32, Cc / 32, Bb), 256>>>(x);
    offset_conv_k<<<dim3(Hh / 2, 4, Bb), 256>>>(x, wp);
    bgen_k<<<dim3(Hh, Bb), 512>>>(bp);
    gemm_k<<<dim3(2, Hh, Bb), 256, G_TOTAL>>>(out);
}

// round 15
// speedup vs baseline: 1.8466x; 1.1417x over previous
#include <cuda_runtime.h>
#include <cuda_fp16.h>
#include <cstdint>

#define Hh   128
#define Ww   128
#define HW   16384
#define Cc   128
#define NP   9
#define OUTC 256
#define Bb   4
#define BK   64
#define NT   18

typedef unsigned long long ull;
typedef unsigned int u32;

// -------- device scratch --------
__device__ float g_offp[4 * Bb * 2 * NP * HW];          // 4-way partial offsets
__device__ float g_offset[Bb * 2 * NP * HW];            // reduced offsets (b,18,H,W)
__device__ __align__(128) __half g_wa[NT * OUTC * BK];  // fp16 A tiles [tile][o][j]
__device__ __align__(128) float g_xT[(size_t)Bb * HW * Cc];  // x transposed: [b][pix][c]

// ---------------- helpers ----------------
__device__ __forceinline__ u32 smem_u32(const void* p) {
    u32 a;
    asm("{ .reg .u64 t; cvta.to.shared.u64 t, %1; cvt.u32.u64 %0, t; }" : "=r"(a) : "l"(p));
    return a;
}
__device__ __forceinline__ void ldsm_x4(u32& r0, u32& r1, u32& r2, u32& r3, u32 addr) {
    asm volatile("ldmatrix.sync.aligned.m8n8.x4.shared.b16 {%0,%1,%2,%3}, [%4];"
                 : "=r"(r0), "=r"(r1), "=r"(r2), "=r"(r3) : "r"(addr));
}
__device__ __forceinline__ void mma_f16(float* d, const u32* a, const u32* b) {
    asm("mma.sync.aligned.m16n8k16.row.col.f32.f16.f16.f32 "
        "{%0,%1,%2,%3},{%4,%5,%6,%7},{%8,%9},{%0,%1,%2,%3};"
        : "+f"(d[0]), "+f"(d[1]), "+f"(d[2]), "+f"(d[3])
        : "r"(a[0]), "r"(a[1]), "r"(a[2]), "r"(a[3]), "r"(b[0]), "r"(b[1]));
}
__device__ __forceinline__ u32 swz(u32 off) { return off ^ ((off >> 3) & 0x70); }

__device__ __forceinline__ void cp_async16(u32 dst, const void* src) {
    asm volatile("cp.async.cg.shared.global [%0], [%1], 16;" :: "r"(dst), "l"(src));
}
#define CP_COMMIT() asm volatile("cp.async.commit_group;" ::: "memory")
#define CP_WAIT0()  asm volatile("cp.async.wait_group 0;" ::: "memory")

// packed f32x2 helpers (offset conv)
__device__ __forceinline__ void ffma2(ull& d, ull a, ull b) {
    asm("fma.rn.f32x2 %0, %1, %2, %0;" : "+l"(d) : "l"(a), "l"(b));
}
__device__ __forceinline__ ull pack2(float lo, float hi) {
    ull r; asm("mov.b64 %0, {%1, %2};" : "=l"(r) : "f"(lo), "f"(hi)); return r;
}
__device__ __forceinline__ float2 unpack2(ull v) {
    float2 f; asm("mov.b64 {%0, %1}, %2;" : "=f"(f.x), "=f"(f.y) : "l"(v)); return f;
}

// ======================================================================
// Kernel 1: w_conv (outc, C, N, 1) -> fp16 tiled A: [tile][o][j]
// ======================================================================
__global__ void wtrans_k(const float* __restrict__ wc) {
    int i = blockIdx.x * 256 + threadIdx.x;
    if (i < NT * OUTC * BK) {
        int j = i & 63;
        int o = (i >> 6) & 255;
        int tt = i >> 14;
        int k = tt * 64 + j;
        int n = k >> 7;
        int c = k & 127;
        g_wa[i] = __float2half_rn(wc[(o * Cc + c) * NP + n]);
    }
}

// ======================================================================
// Kernel 1b: transpose x (b,C,HW) -> xT (b,HW,C)  (proven, unchanged)
// ======================================================================
__global__ void __launch_bounds__(256) xpose_k(const float* __restrict__ x) {
    __shared__ float tile[32][33];
    const int b  = blockIdx.z;
    const int c0 = blockIdx.y * 32;
    const int p0 = blockIdx.x * 32;
    const int tx = threadIdx.x & 31;
    const int ty = threadIdx.x >> 5;   // 0..7

    const float* xb = x + (size_t)b * Cc * HW;
#pragma unroll
    for (int i = 0; i < 32; i += 8)
        tile[ty + i][tx] = xb[(size_t)(c0 + ty + i) * HW + p0 + tx];
    __syncthreads();
    float* xTb = g_xT + (size_t)b * HW * Cc;
#pragma unroll
    for (int i = 0; i < 32; i += 8)
        xTb[(size_t)(p0 + ty + i) * Cc + c0 + tx] = tile[tx][ty + i];
}

// ======================================================================
// Kernel 2: offset conv v3 (proven, unchanged): 4-way channel split
// ======================================================================
__global__ void __launch_bounds__(256) offset_conv_k(
    const float* __restrict__ x,
    const float* __restrict__ wp)
{
    const int y0  = blockIdx.x * 2;
    const int cg  = blockIdx.y;
    const int b   = blockIdx.z;
    const int t   = threadIdx.x;
    const int row = t >> 7;
    const int px  = t & 127;
    const int cbase = cg * 32;

    __shared__ float xr[2][4][132];
    __shared__ float ws2[2][9][18];

    ull acc[9];
#pragma unroll
    for (int p = 0; p < 9; p++) acc[p] = 0ULL;

    const float* xb = x + (size_t)b * Cc * HW;

    auto load_ch = [&](int ci, int s) {
        const int c = cbase + ci;
        for (int i = t; i < 162; i += 256) {
            int k  = i / 18;
            int ch = i % 18;
            ws2[s][k][ch] = wp[ch * (Cc * 9) + c * 9 + k];
        }
        for (int i = t; i < 528; i += 256) {
            int r  = i / 132;
            int cc = i % 132;
            int yy = y0 + r - 1;
            int xx = cc - 1;
            float v = 0.f;
            if (yy >= 0 && yy < Hh && xx >= 0 && xx < Ww)
                v = xb[c * HW + yy * Ww + xx];
            xr[s][r][cc] = v;
        }
    };

    load_ch(0, 0);
    __syncthreads();

    for (int ci = 0; ci < 32; ci++) {
        const int s = ci & 1;
        if (ci + 1 < 32) load_ch(ci + 1, s ^ 1);

#pragma unroll
        for (int k = 0; k < 9; k++) {
            const int ky = k / 3, kx = k % 3;
            float xv = xr[s][row + ky][px + kx];
            ull xd = pack2(xv, xv);
            const ull* wrow = (const ull*)&ws2[s][k][0];
#pragma unroll
            for (int p = 0; p < 9; p++)
                ffma2(acc[p], wrow[p], xd);
        }
        __syncthreads();
    }

    float* P = g_offp + (size_t)((cg * Bb + b) * 18) * HW;
#pragma unroll
    for (int p = 0; p < 9; p++) {
        float2 a = unpack2(acc[p]);
        P[(2 * p)     * HW + (y0 + row) * Ww + px] = a.x;
        P[(2 * p + 1) * HW + (y0 + row) * Ww + px] = a.y;
    }
}

// ======================================================================
// Kernel 2b: osum — reduce 4 partials + bias -> g_offset
// ======================================================================
__global__ void __launch_bounds__(256) osum_k(const float* __restrict__ bp) {
    int i = blockIdx.x * 256 + threadIdx.x;
    if (i >= Bb * 18 * HW) return;
    int pix = i & (HW - 1);
    int ch  = (i >> 14) % 18;
    int b   = i / (18 * HW);
    float v = bp[ch];
#pragma unroll
    for (int cg = 0; cg < 4; cg++)
        v += g_offp[(size_t)((cg * Bb + b) * 18 + ch) * HW + pix];
    g_offset[i] = v;
}

// ======================================================================
// Kernel 3: gg — fused gather + fp16 GEMM.
// CTA (xh, y, b): out[b, 0..255, y, xh*64 .. +63]; 256 thr = 8 warps.
// B generated in-kernel 2 tiles ahead into a 4-slot smem ring.
// ======================================================================
#define F_META  0                      // metaw 9216 | metai 4608 -> 13824
#define F_BQ    13824                  // B ring: 4 x 8192 = 32768
#define F_A0    46592                  // A: 2 x 32768 = 65536
#define F_TOTAL 112128

__global__ void __launch_bounds__(256, 2)
gg_k(float* __restrict__ out)
{
    extern __shared__ char smem[];
    const u32 sb = smem_u32(smem);
    const int t = threadIdx.x;
    const int wid = t >> 5;
    const int lane = t & 31;
    const int xh = blockIdx.x;
    const int y = blockIdx.y;
    const int b = blockIdx.z;

    float4*  metaw = (float4*)(smem + F_META);
    ushort4* metai = (ushort4*)(smem + F_META + 9216);

    // ---- meta prologue: 9 offsets x 64 px ----
    for (int task = t; task < NP * 64; task += 256) {
        int n  = task >> 6;
        int px = task & 63;
        int xx = xh * 64 + px;
        float offr = g_offset[((b * 18 + n) * Hh + y) * Ww + xx];
        float offc = g_offset[((b * 18 + NP + n) * Hh + y) * Ww + xx];
        float pr = (float)y  + (float)(n / 3) + offr;
        float pc = (float)xx + (float)(n % 3) + offc;

        float ltr = floorf(pr), ltc = floorf(pc);
        float rbr = ltr + 1.f,  rbc = ltc + 1.f;
        ltr = fminf(fmaxf(ltr, 0.f), 127.f);
        rbr = fminf(fmaxf(rbr, 0.f), 127.f);
        ltc = fminf(fmaxf(ltc, 0.f), 127.f);
        rbc = fminf(fmaxf(rbc, 0.f), 127.f);
        pr  = fminf(fmaxf(pr, 0.f), 127.f);
        pc  = fminf(fmaxf(pc, 0.f), 127.f);

        float dr_lt = 1.f + (ltr - pr);
        float dr_rb = 1.f - (rbr - pr);
        float dc_lt = 1.f + (ltc - pc);
        float dc_rb = 1.f - (rbc - pc);

        float4 g;
        g.x = dr_lt * dc_lt;
        g.y = dr_rb * dc_rb;
        g.z = dr_lt * dc_rb;
        g.w = dr_rb * dc_lt;
        metaw[task] = g;

        int iltr = (int)ltr, iltc = (int)ltc;
        int irbr = (int)rbr, irbc = (int)rbc;
        ushort4 iv;
        iv.x = (unsigned short)(iltr * Ww + iltc);
        iv.y = (unsigned short)(irbr * Ww + irbc);
        iv.z = (unsigned short)(iltr * Ww + irbc);
        iv.w = (unsigned short)(irbr * Ww + iltc);
        metai[task] = iv;
    }
    __syncthreads();

    const float* xTb = g_xT + (size_t)b * HW * Cc;
    const int c0   = lane * 4;
    const int tsub = lane >> 4;
    const u32 colb = (u32)((c0 & 63) * 2);

    float acc[4][4][4];
#pragma unroll
    for (int i = 0; i < 4; i++)
#pragma unroll
        for (int j = 0; j < 4; j++)
#pragma unroll
            for (int q = 0; q < 4; q++) acc[i][j][q] = 0.f;

    const int bo = (wid & 3) * 64;
    const int bn = (wid >> 2) * 32;

    auto fillA_async = [&](int tile) {
        const u32 dst = sb + F_A0 + (u32)(tile & 1) * 32768;
        const uint4* srcA = (const uint4*)(g_wa + (size_t)tile * OUTC * BK);
#pragma unroll
        for (int i = 0; i < 8; i++) {
            int e = t + i * 256;
            cp_async16(dst + swz((u32)(e * 16)), srcA + e);
        }
        CP_COMMIT();
    };

    // generate one (group n, px) pair into the B ring
    auto gen_pair = [&](int gn, int px) {
        float4  gw = metaw[gn * 64 + px];
        ushort4 gi = metai[gn * 64 + px];
        float4 A = __ldg((const float4*)(xTb + (size_t)gi.x * Cc + c0));
        float4 B = __ldg((const float4*)(xTb + (size_t)gi.y * Cc + c0));
        float4 C = __ldg((const float4*)(xTb + (size_t)gi.z * Cc + c0));
        float4 D = __ldg((const float4*)(xTb + (size_t)gi.w * Cc + c0));
        float v0 = gw.x * A.x + gw.y * B.x + gw.z * C.x + gw.w * D.x;
        float v1 = gw.x * A.y + gw.y * B.y + gw.z * C.y + gw.w * D.y;
        float v2 = gw.x * A.z + gw.y * B.z + gw.z * C.z + gw.w * D.z;
        float v3 = gw.x * A.w + gw.y * B.w + gw.z * C.w + gw.w * D.w;
        u32 p0, p1;
        asm("cvt.rn.f16x2.f32 %0, %1, %2;" : "=r"(p0) : "f"(v1), "f"(v0));
        asm("cvt.rn.f16x2.f32 %0, %1, %2;" : "=r"(p1) : "f"(v3), "f"(v2));
        int s = (2 * gn + tsub) & 3;
        *(uint2*)(smem + F_BQ + s * 8192 + swz((u32)(px * 128) + colb)) = make_uint2(p0, p1);
    };

    // compute tile; if geng >= 0, generate 4 pairs of group geng interleaved
    auto compute = [&](int tile, int geng) {
        const u32 buf  = sb + F_A0 + (u32)(tile & 1) * 32768;
        const u32 bufB = sb + F_BQ + (u32)(tile & 3) * 8192;
        const int halfsel = tile & 1;
        u32 a[4][4], bf[4][2];
#pragma unroll
        for (int ks = 0; ks < 4; ks++) {
            // issue next-group gather for one pair
            float4 GA, GB, GC, GD;
            float4 gw;
            int px = 0;
            if (geng >= 0) {
                px = (wid << 3) + (halfsel << 2) + ks;
                gw = metaw[geng * 64 + px];
                ushort4 gi = metai[geng * 64 + px];
                GA = __ldg((const float4*)(xTb + (size_t)gi.x * Cc + c0));
                GB = __ldg((const float4*)(xTb + (size_t)gi.y * Cc + c0));
                GC = __ldg((const float4*)(xTb + (size_t)gi.z * Cc + c0));
                GD = __ldg((const float4*)(xTb + (size_t)gi.w * Cc + c0));
            }
#pragma unroll
            for (int j = 0; j < 2; j++) {
                int nrow = bn + j * 16 + (lane & 7) + ((lane >> 4) << 3);
                int kb   = ks * 32 + ((lane >> 3) & 1) * 16;
                u32 sw = swz((u32)(nrow * 128 + kb));
                ldsm_x4(bf[2*j][0], bf[2*j][1], bf[2*j+1][0], bf[2*j+1][1], bufB + sw);
            }
#pragma unroll
            for (int mi = 0; mi < 4; mi++) {
                int ar = bo + mi * 16 + (lane & 15);
                int kb = ks * 32 + (lane >> 4) * 16;
                u32 sw = swz((u32)(ar * 128 + kb));
                ldsm_x4(a[mi][0], a[mi][1], a[mi][2], a[mi][3], buf + sw);
            }
#pragma unroll
            for (int mi = 0; mi < 4; mi++)
#pragma unroll
                for (int nt = 0; nt < 4; nt++)
                    mma_f16(acc[mi][nt], a[mi], bf[nt]);

            if (geng >= 0) {
                float v0 = gw.x * GA.x + gw.y * GB.x + gw.z * GC.x + gw.w * GD.x;
                float v1 = gw.x * GA.y + gw.y * GB.y + gw.z * GC.y + gw.w * GD.y;
                float v2 = gw.x * GA.z + gw.y * GB.z + gw.z * GC.z + gw.w * GD.z;
                float v3 = gw.x * GA.w + gw.y * GB.w + gw.z * GC.w + gw.w * GD.w;
                u32 p0, p1;
                asm("cvt.rn.f16x2.f32 %0, %1, %2;" : "=r"(p0) : "f"(v1), "f"(v0));
                asm("cvt.rn.f16x2.f32 %0, %1, %2;" : "=r"(p1) : "f"(v3), "f"(v2));
                int s = (2 * geng + tsub) & 3;
                *(uint2*)(smem + F_BQ + s * 8192 + swz((u32)(px * 128) + colb)) = make_uint2(p0, p1);
            }
        }
    };

    // ---- prologue: A(0) + full group 0 (tiles 0,1) ----
    fillA_async(0);
#pragma unroll
    for (int j = 0; j < 8; j++)
        gen_pair(0, (wid << 3) + j);
    CP_WAIT0();
    __syncthreads();

    // ---- main loop ----
    for (int tile = 0; tile < NT; tile++) {
        if (tile + 1 < NT) fillA_async(tile + 1);
        int geng = (tile / 2 + 1 <= 8) ? (tile / 2 + 1) : -1;
        compute(tile, geng);
        CP_WAIT0();
        __syncthreads();
    }

    // ---- epilogue ----
    const int gq = lane >> 2;
    const int tg = lane & 3;
#pragma unroll
    for (int mi = 0; mi < 4; mi++) {
#pragma unroll
        for (int nt = 0; nt < 4; nt++) {
            int pxo = xh * 64 + bn + nt * 8 + 2 * tg;
            int o0  = bo + mi * 16 + gq;
            int o1  = o0 + 8;
            float* base = out + (size_t)b * OUTC * HW + y * Ww + pxo;
            *(float2*)(base + (size_t)o0 * HW) = make_float2(acc[mi][nt][0], acc[mi][nt][1]);
            *(float2*)(base + (size_t)o1 * HW) = make_float2(acc[mi][nt][2], acc[mi][nt][3]);
        }
    }
}

// ======================================================================
// launch
// ======================================================================
extern "C" void kernel_launch(void* const* d_in, const int* in_sizes, int n_in,
                              void* d_out, int out_size)
{
    const float* x  = nullptr;   // 8388608
    const float* wp = nullptr;   // 20736
    const float* bp = nullptr;   // 18
    const float* wc = nullptr;   // 294912
    for (int i = 0; i < n_in; i++) {
        switch (in_sizes[i]) {
            case 8388608: x  = (const float*)d_in[i]; break;
            case 20736:   wp = (const float*)d_in[i]; break;
            case 18:      bp = (const float*)d_in[i]; break;
            case 294912:  wc = (const float*)d_in[i]; break;
            default: break;
        }
    }
    if (!x)  x  = (const float*)d_in[0];
    if (!wp) wp = (const float*)d_in[1];
    if (!bp) bp = (const float*)d_in[2];
    if (!wc) wc = (const float*)d_in[3];

    float* out = (float*)d_out;

    cudaFuncSetAttribute(gg_k,
                         cudaFuncAttributeMaxDynamicSharedMemorySize, F_TOTAL);

    wtrans_k<<<(NT * OUTC * BK + 255) / 256, 256>>>(wc);
    xpose_k<<<dim3(HW / 32, Cc / 32, Bb), 256>>>(x);
    offset_conv_k<<<dim3(Hh / 2, 4, Bb), 256>>>(x, wp);
    osum_k<<<(Bb * 18 * HW + 255) / 256, 256>>>(bp);
    gg_k<<<dim3(2, Hh, Bb), 256, F_TOTAL>>>(out);
}

// round 16
// speedup vs baseline: 1.8871x; 1.0219x over previous
#include <cuda_runtime.h>
#include <cuda_fp16.h>
#include <cstdint>

#define Hh   128
#define Ww   128
#define HW   16384
#define Cc   128
#define NP   9
#define OUTC 256
#define Bb   4
#define BK   64
#define NT   18

typedef unsigned long long ull;
typedef unsigned int u32;

// -------- device scratch --------
__device__ float g_offp[4 * Bb * 2 * NP * HW];          // 4-way partial offsets
__device__ float g_offset[Bb * 2 * NP * HW];            // reduced offsets (b,18,H,W)
__device__ __align__(128) __half g_wa[NT * OUTC * BK];  // fp16 A tiles [tile][o][j]
__device__ __align__(128) __half g_xTh[(size_t)Bb * HW * Cc]; // fp16 xT: [b][pix][c]

// ---------------- helpers ----------------
__device__ __forceinline__ u32 smem_u32(const void* p) {
    u32 a;
    asm("{ .reg .u64 t; cvta.to.shared.u64 t, %1; cvt.u32.u64 %0, t; }" : "=r"(a) : "l"(p));
    return a;
}
__device__ __forceinline__ void ldsm_x4(u32& r0, u32& r1, u32& r2, u32& r3, u32 addr) {
    asm volatile("ldmatrix.sync.aligned.m8n8.x4.shared.b16 {%0,%1,%2,%3}, [%4];"
                 : "=r"(r0), "=r"(r1), "=r"(r2), "=r"(r3) : "r"(addr));
}
__device__ __forceinline__ void mma_f16(float* d, const u32* a, const u32* b) {
    asm("mma.sync.aligned.m16n8k16.row.col.f32.f16.f16.f32 "
        "{%0,%1,%2,%3},{%4,%5,%6,%7},{%8,%9},{%0,%1,%2,%3};"
        : "+f"(d[0]), "+f"(d[1]), "+f"(d[2]), "+f"(d[3])
        : "r"(a[0]), "r"(a[1]), "r"(a[2]), "r"(a[3]), "r"(b[0]), "r"(b[1]));
}
__device__ __forceinline__ u32 swz(u32 off) { return off ^ ((off >> 3) & 0x70); }

__device__ __forceinline__ void cp_async16(u32 dst, const void* src) {
    asm volatile("cp.async.cg.shared.global [%0], [%1], 16;" :: "r"(dst), "l"(src));
}
#define CP_COMMIT() asm volatile("cp.async.commit_group;" ::: "memory")
#define CP_WAIT0()  asm volatile("cp.async.wait_group 0;" ::: "memory")

// packed f32x2 helpers (offset conv)
__device__ __forceinline__ void ffma2(ull& d, ull a, ull b) {
    asm("fma.rn.f32x2 %0, %1, %2, %0;" : "+l"(d) : "l"(a), "l"(b));
}
__device__ __forceinline__ ull pack2(float lo, float hi) {
    ull r; asm("mov.b64 %0, {%1, %2};" : "=l"(r) : "f"(lo), "f"(hi)); return r;
}
__device__ __forceinline__ float2 unpack2(ull v) {
    float2 f; asm("mov.b64 {%0, %1}, %2;" : "=f"(f.x), "=f"(f.y) : "l"(v)); return f;
}

// ======================================================================
// Kernel 1: w_conv (outc, C, N, 1) -> fp16 tiled A: [tile][o][j]
// ======================================================================
__global__ void wtrans_k(const float* __restrict__ wc) {
    int i = blockIdx.x * 256 + threadIdx.x;
    if (i < NT * OUTC * BK) {
        int j = i & 63;
        int o = (i >> 6) & 255;
        int tt = i >> 14;
        int k = tt * 64 + j;
        int n = k >> 7;
        int c = k & 127;
        g_wa[i] = __float2half_rn(wc[(o * Cc + c) * NP + n]);
    }
}

// ======================================================================
// Kernel 1b: transpose x (b,C,HW) -> fp16 xT (b,HW,C)
// ======================================================================
__global__ void __launch_bounds__(256) xpose_k(const float* __restrict__ x) {
    __shared__ float tile[32][33];
    const int b  = blockIdx.z;
    const int c0 = blockIdx.y * 32;
    const int p0 = blockIdx.x * 32;
    const int tx = threadIdx.x & 31;
    const int ty = threadIdx.x >> 5;   // 0..7

    const float* xb = x + (size_t)b * Cc * HW;
#pragma unroll
    for (int i = 0; i < 32; i += 8)
        tile[ty + i][tx] = xb[(size_t)(c0 + ty + i) * HW + p0 + tx];
    __syncthreads();
    __half* xTb = g_xTh + (size_t)b * HW * Cc;
#pragma unroll
    for (int i = 0; i < 32; i += 8)
        xTb[(size_t)(p0 + ty + i) * Cc + c0 + tx] = __float2half_rn(tile[tx][ty + i]);
}

// ======================================================================
// Kernel 2: offset conv v3 (proven, unchanged): 4-way channel split
// ======================================================================
__global__ void __launch_bounds__(256) offset_conv_k(
    const float* __restrict__ x,
    const float* __restrict__ wp)
{
    const int y0  = blockIdx.x * 2;
    const int cg  = blockIdx.y;
    const int b   = blockIdx.z;
    const int t   = threadIdx.x;
    const int row = t >> 7;
    const int px  = t & 127;
    const int cbase = cg * 32;

    __shared__ float xr[2][4][132];
    __shared__ float ws2[2][9][18];

    ull acc[9];
#pragma unroll
    for (int p = 0; p < 9; p++) acc[p] = 0ULL;

    const float* xb = x + (size_t)b * Cc * HW;

    auto load_ch = [&](int ci, int s) {
        const int c = cbase + ci;
        for (int i = t; i < 162; i += 256) {
            int k  = i / 18;
            int ch = i % 18;
            ws2[s][k][ch] = wp[ch * (Cc * 9) + c * 9 + k];
        }
        for (int i = t; i < 528; i += 256) {
            int r  = i / 132;
            int cc = i % 132;
            int yy = y0 + r - 1;
            int xx = cc - 1;
            float v = 0.f;
            if (yy >= 0 && yy < Hh && xx >= 0 && xx < Ww)
                v = xb[c * HW + yy * Ww + xx];
            xr[s][r][cc] = v;
        }
    };

    load_ch(0, 0);
    __syncthreads();

    for (int ci = 0; ci < 32; ci++) {
        const int s = ci & 1;
        if (ci + 1 < 32) load_ch(ci + 1, s ^ 1);

#pragma unroll
        for (int k = 0; k < 9; k++) {
            const int ky = k / 3, kx = k % 3;
            float xv = xr[s][row + ky][px + kx];
            ull xd = pack2(xv, xv);
            const ull* wrow = (const ull*)&ws2[s][k][0];
#pragma unroll
            for (int p = 0; p < 9; p++)
                ffma2(acc[p], wrow[p], xd);
        }
        __syncthreads();
    }

    float* P = g_offp + (size_t)((cg * Bb + b) * 18) * HW;
#pragma unroll
    for (int p = 0; p < 9; p++) {
        float2 a = unpack2(acc[p]);
        P[(2 * p)     * HW + (y0 + row) * Ww + px] = a.x;
        P[(2 * p + 1) * HW + (y0 + row) * Ww + px] = a.y;
    }
}

// ======================================================================
// Kernel 2b: osum — reduce 4 partials + bias -> g_offset
// ======================================================================
__global__ void __launch_bounds__(256) osum_k(const float* __restrict__ bp) {
    int i = blockIdx.x * 256 + threadIdx.x;
    if (i >= Bb * 18 * HW) return;
    int pix = i & (HW - 1);
    int ch  = (i >> 14) % 18;
    int b   = i / (18 * HW);
    float v = bp[ch];
#pragma unroll
    for (int cg = 0; cg < 4; cg++)
        v += g_offp[(size_t)((cg * Bb + b) * 18 + ch) * HW + pix];
    g_offset[i] = v;
}

// ======================================================================
// Kernel 3: gg — fused gather (fp16 xT) + fp16 GEMM.
// CTA (xh, y, b): out[b, 0..255, y, xh*64 .. +63]; 256 thr = 8 warps.
// B generated in-kernel 2 tiles ahead into a 4-slot smem ring.
// ======================================================================
#define F_META  0                      // metaw 9216 | metai 4608 -> 13824
#define F_BQ    13824                  // B ring: 4 x 8192 = 32768
#define F_A0    46592                  // A: 2 x 32768 = 65536
#define F_TOTAL 112128

__global__ void __launch_bounds__(256, 2)
gg_k(float* __restrict__ out)
{
    extern __shared__ char smem[];
    const u32 sb = smem_u32(smem);
    const int t = threadIdx.x;
    const int wid = t >> 5;
    const int lane = t & 31;
    const int xh = blockIdx.x;
    const int y = blockIdx.y;
    const int b = blockIdx.z;

    float4*  metaw = (float4*)(smem + F_META);
    ushort4* metai = (ushort4*)(smem + F_META + 9216);

    // ---- meta prologue: 9 offsets x 64 px ----
    for (int task = t; task < NP * 64; task += 256) {
        int n  = task >> 6;
        int px = task & 63;
        int xx = xh * 64 + px;
        float offr = g_offset[((b * 18 + n) * Hh + y) * Ww + xx];
        float offc = g_offset[((b * 18 + NP + n) * Hh + y) * Ww + xx];
        float pr = (float)y  + (float)(n / 3) + offr;
        float pc = (float)xx + (float)(n % 3) + offc;

        float ltr = floorf(pr), ltc = floorf(pc);
        float rbr = ltr + 1.f,  rbc = ltc + 1.f;
        ltr = fminf(fmaxf(ltr, 0.f), 127.f);
        rbr = fminf(fmaxf(rbr, 0.f), 127.f);
        ltc = fminf(fmaxf(ltc, 0.f), 127.f);
        rbc = fminf(fmaxf(rbc, 0.f), 127.f);
        pr  = fminf(fmaxf(pr, 0.f), 127.f);
        pc  = fminf(fmaxf(pc, 0.f), 127.f);

        float dr_lt = 1.f + (ltr - pr);
        float dr_rb = 1.f - (rbr - pr);
        float dc_lt = 1.f + (ltc - pc);
        float dc_rb = 1.f - (rbc - pc);

        float4 g;
        g.x = dr_lt * dc_lt;
        g.y = dr_rb * dc_rb;
        g.z = dr_lt * dc_rb;
        g.w = dr_rb * dc_lt;
        metaw[task] = g;

        int iltr = (int)ltr, iltc = (int)ltc;
        int irbr = (int)rbr, irbc = (int)rbc;
        ushort4 iv;
        iv.x = (unsigned short)(iltr * Ww + iltc);
        iv.y = (unsigned short)(irbr * Ww + irbc);
        iv.z = (unsigned short)(iltr * Ww + irbc);
        iv.w = (unsigned short)(irbr * Ww + iltc);
        metai[task] = iv;
    }
    __syncthreads();

    const __half* xTb = g_xTh + (size_t)b * HW * Cc;
    const int c0   = lane * 4;
    const int tsub = lane >> 4;
    const u32 colb = (u32)((c0 & 63) * 2);

    float acc[4][4][4];
#pragma unroll
    for (int i = 0; i < 4; i++)
#pragma unroll
        for (int j = 0; j < 4; j++)
#pragma unroll
            for (int q = 0; q < 4; q++) acc[i][j][q] = 0.f;

    const int bo = (wid & 3) * 64;
    const int bn = (wid >> 2) * 32;

    auto fillA_async = [&](int tile) {
        const u32 dst = sb + F_A0 + (u32)(tile & 1) * 32768;
        const uint4* srcA = (const uint4*)(g_wa + (size_t)tile * OUTC * BK);
#pragma unroll
        for (int i = 0; i < 8; i++) {
            int e = t + i * 256;
            cp_async16(dst + swz((u32)(e * 16)), srcA + e);
        }
        CP_COMMIT();
    };

    // combine 4 fp16-corner uint2s with bilinear weights -> packed f16x2 pair
    auto combine_pack = [&](float4 gw, uint2 Au, uint2 Bu, uint2 Cu, uint2 Du,
                            u32& p0, u32& p1) {
        float2 a01 = __half22float2(*(__half2*)&Au.x);
        float2 a23 = __half22float2(*(__half2*)&Au.y);
        float2 b01 = __half22float2(*(__half2*)&Bu.x);
        float2 b23 = __half22float2(*(__half2*)&Bu.y);
        float2 c01 = __half22float2(*(__half2*)&Cu.x);
        float2 c23 = __half22float2(*(__half2*)&Cu.y);
        float2 d01 = __half22float2(*(__half2*)&Du.x);
        float2 d23 = __half22float2(*(__half2*)&Du.y);
        float v0 = gw.x * a01.x + gw.y * b01.x + gw.z * c01.x + gw.w * d01.x;
        float v1 = gw.x * a01.y + gw.y * b01.y + gw.z * c01.y + gw.w * d01.y;
        float v2 = gw.x * a23.x + gw.y * b23.x + gw.z * c23.x + gw.w * d23.x;
        float v3 = gw.x * a23.y + gw.y * b23.y + gw.z * c23.y + gw.w * d23.y;
        asm("cvt.rn.f16x2.f32 %0, %1, %2;" : "=r"(p0) : "f"(v1), "f"(v0));
        asm("cvt.rn.f16x2.f32 %0, %1, %2;" : "=r"(p1) : "f"(v3), "f"(v2));
    };

    // generate one (group n, px) pair into the B ring
    auto gen_pair = [&](int gn, int px) {
        float4  gw = metaw[gn * 64 + px];
        ushort4 gi = metai[gn * 64 + px];
        uint2 Au = __ldg((const uint2*)(xTb + (size_t)gi.x * Cc + c0));
        uint2 Bu = __ldg((const uint2*)(xTb + (size_t)gi.y * Cc + c0));
        uint2 Cu = __ldg((const uint2*)(xTb + (size_t)gi.z * Cc + c0));
        uint2 Du = __ldg((const uint2*)(xTb + (size_t)gi.w * Cc + c0));
        u32 p0, p1;
        combine_pack(gw, Au, Bu, Cu, Du, p0, p1);
        int s = (2 * gn + tsub) & 3;
        *(uint2*)(smem + F_BQ + s * 8192 + swz((u32)(px * 128) + colb)) = make_uint2(p0, p1);
    };

    // compute tile; if geng >= 0, generate 4 pairs of group geng interleaved
    auto compute = [&](int tile, int geng) {
        const u32 buf  = sb + F_A0 + (u32)(tile & 1) * 32768;
        const u32 bufB = sb + F_BQ + (u32)(tile & 3) * 8192;
        const int halfsel = tile & 1;
        u32 a[4][4], bf[4][2];
#pragma unroll
        for (int ks = 0; ks < 4; ks++) {
            // issue next-group gather for one pair
            uint2 GA, GB, GC, GD;
            float4 gw;
            int px = 0;
            if (geng >= 0) {
                px = (wid << 3) + (halfsel << 2) + ks;
                gw = metaw[geng * 64 + px];
                ushort4 gi = metai[geng * 64 + px];
                GA = __ldg((const uint2*)(xTb + (size_t)gi.x * Cc + c0));
                GB = __ldg((const uint2*)(xTb + (size_t)gi.y * Cc + c0));
                GC = __ldg((const uint2*)(xTb + (size_t)gi.z * Cc + c0));
                GD = __ldg((const uint2*)(xTb + (size_t)gi.w * Cc + c0));
            }
#pragma unroll
            for (int j = 0; j < 2; j++) {
                int nrow = bn + j * 16 + (lane & 7) + ((lane >> 4) << 3);
                int kb   = ks * 32 + ((lane >> 3) & 1) * 16;
                u32 sw = swz((u32)(nrow * 128 + kb));
                ldsm_x4(bf[2*j][0], bf[2*j][1], bf[2*j+1][0], bf[2*j+1][1], bufB + sw);
            }
#pragma unroll
            for (int mi = 0; mi < 4; mi++) {
                int ar = bo + mi * 16 + (lane & 15);
                int kb = ks * 32 + (lane >> 4) * 16;
                u32 sw = swz((u32)(ar * 128 + kb));
                ldsm_x4(a[mi][0], a[mi][1], a[mi][2], a[mi][3], buf + sw);
            }
#pragma unroll
            for (int mi = 0; mi < 4; mi++)
#pragma unroll
                for (int nt = 0; nt < 4; nt++)
                    mma_f16(acc[mi][nt], a[mi], bf[nt]);

            if (geng >= 0) {
                u32 p0, p1;
                combine_pack(gw, GA, GB, GC, GD, p0, p1);
                int s = (2 * geng + tsub) & 3;
                *(uint2*)(smem + F_BQ + s * 8192 + swz((u32)(px * 128) + colb)) = make_uint2(p0, p1);
            }
        }
    };

    // ---- prologue: A(0) + full group 0 (tiles 0,1) ----
    fillA_async(0);
#pragma unroll
    for (int j = 0; j < 8; j++)
        gen_pair(0, (wid << 3) + j);
    CP_WAIT0();
    __syncthreads();

    // ---- main loop ----
    for (int tile = 0; tile < NT; tile++) {
        if (tile + 1 < NT) fillA_async(tile + 1);
        int geng = (tile / 2 + 1 <= 8) ? (tile / 2 + 1) : -1;
        compute(tile, geng);
        CP_WAIT0();
        __syncthreads();
    }

    // ---- epilogue ----
    const int gq = lane >> 2;
    const int tg = lane & 3;
#pragma unroll
    for (int mi = 0; mi < 4; mi++) {
#pragma unroll
        for (int nt = 0; nt < 4; nt++) {
            int pxo = xh * 64 + bn + nt * 8 + 2 * tg;
            int o0  = bo + mi * 16 + gq;
            int o1  = o0 + 8;
            float* base = out + (size_t)b * OUTC * HW + y * Ww + pxo;
            *(float2*)(base + (size_t)o0 * HW) = make_float2(acc[mi][nt][0], acc[mi][nt][1]);
            *(float2*)(base + (size_t)o1 * HW) = make_float2(acc[mi][nt][2], acc[mi][nt][3]);
        }
    }
}

// ======================================================================
// launch
// ======================================================================
extern "C" void kernel_launch(void* const* d_in, const int* in_sizes, int n_in,
                              void* d_out, int out_size)
{
    const float* x  = nullptr;   // 8388608
    const float* wp = nullptr;   // 20736
    const float* bp = nullptr;   // 18
    const float* wc = nullptr;   // 294912
    for (int i = 0; i < n_in; i++) {
        switch (in_sizes[i]) {
            case 8388608: x  = (const float*)d_in[i]; break;
            case 20736:   wp = (const float*)d_in[i]; break;
            case 18:      bp = (const float*)d_in[i]; break;
            case 294912:  wc = (const float*)d_in[i]; break;
            default: break;
        }
    }
    if (!x)  x  = (const float*)d_in[0];
    if (!wp) wp = (const float*)d_in[1];
    if (!bp) bp = (const float*)d_in[2];
    if (!wc) wc = (const float*)d_in[3];

    float* out = (float*)d_out;

    cudaFuncSetAttribute(gg_k,
                         cudaFuncAttributeMaxDynamicSharedMemorySize, F_TOTAL);

    wtrans_k<<<(NT * OUTC * BK + 255) / 256, 256>>>(wc);
    xpose_k<<<dim3(HW / 32, Cc / 32, Bb), 256>>>(x);
    offset_conv_k<<<dim3(Hh / 2, 4, Bb), 256>>>(x, wp);
    osum_k<<<(Bb * 18 * HW + 255) / 256, 256>>>(bp);
    gg_k<<<dim3(2, Hh, Bb), 256, F_TOTAL>>>(out);
}